// round 12
// baseline (speedup 1.0000x reference)
#include <cuda_runtime.h>
#include <cuda_fp16.h>
#include <cstdint>

#define Bsz 8
#define Nseq 1024
#define Cdim 768
#define Hh 12
#define HD 64
#define RANK 8
#define SCALE 0.125f
#define Mrows (Bsz * Nseq)          // 8192

#define QKV_ELEMS (Bsz * Hh * Nseq * HD)   // 6291456

// float-slot offsets into g_scratch
#define F_XHI  ((size_t)0)
#define F_XLO  (F_XHI + QKV_ELEMS / 2)
#define F_WQH  (F_XLO + QKV_ELEMS / 2)
#define F_WPH  (F_WQH + (size_t)(3 * Cdim * Cdim) / 2)
#define F_QH   (F_WPH + (size_t)(Cdim * Cdim) / 2)
#define F_QL   (F_QH + QKV_ELEMS / 2)
#define F_KH   (F_QL + QKV_ELEMS / 2)
#define F_VH   (F_KH + QKV_ELEMS / 2)
#define F_OHI  (F_VH + QKV_ELEMS / 2)
#define F_OLO  (F_OHI + QKV_ELEMS / 2)
#define SCRATCH_FLOATS (F_OLO + QKV_ELEMS / 2)

__device__ float g_scratch[SCRATCH_FLOATS];

// ===========================================================================
// helpers
// ===========================================================================
__device__ __forceinline__ uint32_t smem_u32(const void* p) {
    uint32_t a;
    asm("{ .reg .u64 t; cvta.to.shared.u64 t, %1; cvt.u32.u64 %0, t; }" : "=r"(a) : "l"(p));
    return a;
}
__device__ __forceinline__ void cp_async16(uint32_t dst, const void* src) {
    asm volatile("cp.async.cg.shared.global [%0], [%1], 16;" :: "r"(dst), "l"(src) : "memory");
}
__device__ __forceinline__ void ldsm_x4(uint32_t* r, uint32_t addr) {
    asm volatile("ldmatrix.sync.aligned.m8n8.x4.shared.b16 {%0,%1,%2,%3}, [%4];"
        : "=r"(r[0]), "=r"(r[1]), "=r"(r[2]), "=r"(r[3]) : "r"(addr));
}
__device__ __forceinline__ void mma_f16(float* c, const uint32_t* a, const uint32_t* b) {
    asm volatile("mma.sync.aligned.m16n8k16.row.col.f32.f16.f16.f32 "
        "{%0,%1,%2,%3}, {%4,%5,%6,%7}, {%8,%9}, {%0,%1,%2,%3};"
        : "+f"(c[0]), "+f"(c[1]), "+f"(c[2]), "+f"(c[3])
        : "r"(a[0]), "r"(a[1]), "r"(a[2]), "r"(a[3]), "r"(b[0]), "r"(b[1]));
}

__device__ __forceinline__ void splitpair_h(float x, float y, uint32_t& hi, uint32_t& lo) {
    __half2 h, l;
    h.x = __float2half_rn(x);
    h.y = __float2half_rn(y);
    l.x = __float2half_rn(x - __half2float(h.x));
    l.y = __float2half_rn(y - __half2float(h.y));
    hi = *reinterpret_cast<uint32_t*>(&h);
    lo = *reinterpret_cast<uint32_t*>(&l);
}
__device__ __forceinline__ uint32_t pack2h(float x, float y) {
    __half2 h;
    h.x = __float2half_rn(x);
    h.y = __float2half_rn(y);
    return *reinterpret_cast<uint32_t*>(&h);
}

// ===========================================================================
// fp16 split (x only)
// ===========================================================================
__global__ void __launch_bounds__(256) split_kernel(
    const float* __restrict__ in, uint32_t* __restrict__ hi,
    uint32_t* __restrict__ lo)
{
    int i = blockIdx.x * 256 + threadIdx.x;
    float4 v = ((const float4*)in)[i];
    uint32_t h0, l0, h1, l1;
    splitpair_h(v.x, v.y, h0, l0);
    splitpair_h(v.z, v.w, h1, l1);
    hi[i * 2]     = h0;
    hi[i * 2 + 1] = h1;
    lo[i * 2]     = l0;
    lo[i * 2 + 1] = l1;
}

// ===========================================================================
// W_eff = W + B*A  (rank-8 update), packed to fp16 hi only.
// ===========================================================================
__global__ void __launch_bounds__(128) weff_kernel(
    const float* __restrict__ w, uint32_t* __restrict__ hi,
    const float* __restrict__ b0, const float* __restrict__ a0,
    const float* __restrict__ b1, const float* __restrict__ a1,
    const float* __restrict__ b2, const float* __restrict__ a2)
{
    int d = blockIdx.x;
    int sec = d / Cdim;
    int dd = d - sec * Cdim;
    const float* bb = (sec == 0) ? b0 : (sec == 1) ? b1 : b2;
    const float* aa = (sec == 0) ? a0 : (sec == 1) ? a1 : a2;
    float bv[8];
    #pragma unroll
    for (int r = 0; r < 8; r++) bv[r] = bb[dd * 8 + r];
    int c0 = threadIdx.x * 6;
    float v[6];
    #pragma unroll
    for (int i = 0; i < 6; i++) v[i] = w[(size_t)d * Cdim + c0 + i];
    #pragma unroll
    for (int r = 0; r < 8; r++) {
        float br = bv[r];
        const float* ar = aa + (size_t)r * Cdim + c0;
        #pragma unroll
        for (int i = 0; i < 6; i++) v[i] += br * ar[i];
    }
    #pragma unroll
    for (int p = 0; p < 3; p++)
        hi[(size_t)d * (Cdim / 2) + (c0 >> 1) + p] = pack2h(v[2 * p], v[2 * p + 1]);
}

// ===========================================================================
// fp16 2-term NT GEMM, 128x128 tile, BK=32, 8 warps, cp.async + ldmatrix,
// 2 CTAs/SM.
// ===========================================================================
#define GK768_U32 384
#define SROW 20
#define STAGE_U32 (3 * 128 * SROW)          // Ahi, Alo, Bhi
#define STAGE_BYTES (STAGE_U32 * 4)         // 30720
#define GEMM_SMEM (2 * STAGE_BYTES)         // 61440

template <int MODE>
__global__ void __launch_bounds__(256, 2) gemm_f16x2_kernel(
    const uint32_t* __restrict__ Ahi, const uint32_t* __restrict__ Alo,
    const uint32_t* __restrict__ Bhi,
    const float* __restrict__ bias,
    float* __restrict__ outf,
    uint32_t* __restrict__ Qho, uint32_t* __restrict__ Qlo2,
    uint32_t* __restrict__ Kho, uint32_t* __restrict__ Vho)
{
    extern __shared__ uint32_t sm[];
    uint32_t sbase = smem_u32(sm);
    int tid = threadIdx.x;
    int wid = tid >> 5, lane = tid & 31;
    int wm = wid >> 2, wn = wid & 3;
    int m0 = blockIdx.y * 128, n0 = blockIdx.x * 128;
    int g = lane >> 2, tg = lane & 3;

    float C[4][4][4];
    #pragma unroll
    for (int a = 0; a < 4; a++)
        #pragma unroll
        for (int b = 0; b < 4; b++)
            #pragma unroll
            for (int q = 0; q < 4; q++) C[a][b][q] = 0.f;

    int row_l = tid >> 2, kq_l = tid & 3;
    int row_h = (tid + 256) >> 2;

    uint32_t d0b = (row_l * SROW + kq_l * 4) * 4;
    uint32_t d1b = (row_h * SROW + kq_l * 4) * 4;
    const uint32_t* Asrc0 = Ahi + (size_t)(m0 + row_l) * GK768_U32 + kq_l * 4;
    const uint32_t* Lsrc0 = Alo + (size_t)(m0 + row_l) * GK768_U32 + kq_l * 4;
    const uint32_t* Bsrc0 = Bhi + (size_t)(n0 + row_l) * GK768_U32 + kq_l * 4;
    const uint32_t* Asrc1 = Ahi + (size_t)(m0 + row_h) * GK768_U32 + kq_l * 4;
    const uint32_t* Lsrc1 = Alo + (size_t)(m0 + row_h) * GK768_U32 + kq_l * 4;
    const uint32_t* Bsrc1 = Bhi + (size_t)(n0 + row_h) * GK768_U32 + kq_l * 4;

    // ldmatrix per-lane base addresses (bytes)
    // A pattern: m1 = +8 rows, m2 = +16B (k+8)
    uint32_t aAddr = sbase +
        (uint32_t)((wm * 64 + (lane & 7) + ((lane >> 3) & 1) * 8) * SROW * 4) +
        (uint32_t)((lane >> 4) * 16);
    // B pattern: m1 = +16B (k+8), m2 = +8 rows
    uint32_t bAddr = sbase + 5120 * 4 +
        (uint32_t)((wn * 32 + (lane & 7) + ((lane & 16) >> 1)) * SROW * 4) +
        (uint32_t)(((lane >> 3) & 1) * 16);

    // prologue: chunk 0 -> buffer 0
    {
        uint32_t db = sbase;
        cp_async16(db + d0b,                Asrc0);
        cp_async16(db + 2560 * 4 + d0b,     Lsrc0);
        cp_async16(db + 5120 * 4 + d0b,     Bsrc0);
        cp_async16(db + d1b,                Asrc1);
        cp_async16(db + 2560 * 4 + d1b,     Lsrc1);
        cp_async16(db + 5120 * 4 + d1b,     Bsrc1);
        asm volatile("cp.async.commit_group;" ::: "memory");
    }

    for (int c = 0; c < 24; c++) {
        int s = c & 1;
        if (c < 23) {
            uint32_t off = (c + 1) * 16;
            uint32_t db = sbase + (s ^ 1) * STAGE_BYTES;
            cp_async16(db + d0b,            Asrc0 + off);
            cp_async16(db + 2560 * 4 + d0b, Lsrc0 + off);
            cp_async16(db + 5120 * 4 + d0b, Bsrc0 + off);
            cp_async16(db + d1b,            Asrc1 + off);
            cp_async16(db + 2560 * 4 + d1b, Lsrc1 + off);
            cp_async16(db + 5120 * 4 + d1b, Bsrc1 + off);
            asm volatile("cp.async.commit_group;" ::: "memory");
            asm volatile("cp.async.wait_group 1;" ::: "memory");
        } else {
            asm volatile("cp.async.wait_group 0;" ::: "memory");
        }
        __syncthreads();

        uint32_t bufo = (uint32_t)(s * STAGE_BYTES);
        #pragma unroll
        for (int ks = 0; ks < 2; ks++) {
            uint32_t ko = (uint32_t)(ks * 32);
            uint32_t ah[4][4], al[4][4], bh[4][2];
            #pragma unroll
            for (int mi = 0; mi < 4; mi++)
                ldsm_x4(ah[mi], aAddr + bufo + mi * (16 * SROW * 4) + ko);
            #pragma unroll
            for (int mi = 0; mi < 4; mi++)
                ldsm_x4(al[mi], aAddr + bufo + 2560 * 4 + mi * (16 * SROW * 4) + ko);
            #pragma unroll
            for (int p = 0; p < 2; p++) {
                uint32_t t[4];
                ldsm_x4(t, bAddr + bufo + p * (16 * SROW * 4) + ko);
                bh[2 * p][0] = t[0]; bh[2 * p][1] = t[1];
                bh[2 * p + 1][0] = t[2]; bh[2 * p + 1][1] = t[3];
            }
            #pragma unroll
            for (int mi = 0; mi < 4; mi++)
                #pragma unroll
                for (int ni = 0; ni < 4; ni++)
                    mma_f16(C[mi][ni], ah[mi], bh[ni]);
            #pragma unroll
            for (int mi = 0; mi < 4; mi++)
                #pragma unroll
                for (int ni = 0; ni < 4; ni++)
                    mma_f16(C[mi][ni], al[mi], bh[ni]);
        }
        __syncthreads();
    }

    // ------------------------------ epilogue ------------------------------
    int sct = 0, dbase = 0;
    if (MODE == 0) {
        sct = n0 / Cdim;
        dbase = n0 - sct * Cdim;
    }
    #pragma unroll
    for (int mi = 0; mi < 4; mi++) {
        int m_a = m0 + wm * 64 + mi * 16 + g;
        int m_b = m_a + 8;
        int ba = m_a >> 10, na = m_a & 1023;
        int bb = m_b >> 10, nb = m_b & 1023;
        #pragma unroll
        for (int ni = 0; ni < 4; ni++) {
            int dloc = wn * 32 + ni * 8 + tg * 2;
            int d0 = n0 + dloc;
            float2 va, vb2;
            va.x  = C[mi][ni][0] + bias[d0];
            va.y  = C[mi][ni][1] + bias[d0 + 1];
            vb2.x = C[mi][ni][2] + bias[d0];
            vb2.y = C[mi][ni][3] + bias[d0 + 1];
            if (MODE == 0) {
                int dd0 = dbase + dloc;
                int h = dd0 >> 6, hd = dd0 & 63;
                size_t iA = (((size_t)(ba * Hh + h) * Nseq) + na) * 32 + (hd >> 1);
                size_t iB = (((size_t)(bb * Hh + h) * Nseq) + nb) * 32 + (hd >> 1);
                if (sct == 0) {
                    va.x *= SCALE; va.y *= SCALE; vb2.x *= SCALE; vb2.y *= SCALE;
                    uint32_t hA, lA, hB, lB;
                    splitpair_h(va.x, va.y, hA, lA);
                    splitpair_h(vb2.x, vb2.y, hB, lB);
                    Qho[iA] = hA; Qlo2[iA] = lA;
                    Qho[iB] = hB; Qlo2[iB] = lB;
                } else {
                    uint32_t* th = (sct == 1) ? Kho : Vho;
                    th[iA] = pack2h(va.x, va.y);
                    th[iB] = pack2h(vb2.x, vb2.y);
                }
            } else {
                *(float2*)(outf + (size_t)m_a * Cdim + d0) = va;
                *(float2*)(outf + (size_t)m_b * Cdim + d0) = vb2;
            }
        }
    }
}

// ===========================================================================
// Flash attention via mma.sync fp16 2-term + ldmatrix fragment loads.
// ===========================================================================
#define KS_STRIDE 36               // u32; 144 B (16B-aligned, conflict-free)
#define VS_STRIDE 68               // u32; 272 B (16B-aligned, conflict-free)
#define ATT_SMEM_U32 (128 * KS_STRIDE + 64 * VS_STRIDE)   // 8960
#define ATT_SMEM (ATT_SMEM_U32 * 4)

__global__ void __launch_bounds__(256) attn_mma_kernel(
    const uint32_t* __restrict__ Qh, const uint32_t* __restrict__ Ql,
    const uint32_t* __restrict__ Kh, const uint32_t* __restrict__ Vh,
    uint32_t* __restrict__ Ohi, uint32_t* __restrict__ Olo)
{
    extern __shared__ uint32_t sm[];
    uint32_t* Khs = sm;
    uint32_t* Vhs = sm + 128 * KS_STRIDE;
    uint16_t* Vh16 = (uint16_t*)Vhs;

    int bh = blockIdx.y, qt = blockIdx.x;
    int tid = threadIdx.x, wid = tid >> 5, lane = tid & 31;
    int g = lane >> 2, tg = lane & 3;

    // B-pattern ldmatrix lane addresses
    uint32_t kAddr = smem_u32(Khs) +
        (uint32_t)(((lane & 7) + ((lane & 16) >> 1)) * KS_STRIDE * 4) +
        (uint32_t)(((lane >> 3) & 1) * 16);
    uint32_t vAddr = smem_u32(Vhs) +
        (uint32_t)(((lane & 7) + ((lane & 16) >> 1)) * VS_STRIDE * 4) +
        (uint32_t)(((lane >> 3) & 1) * 16);

    uint32_t qh[4][4], ql[4][4];
    {
        const uint32_t* qb  = Qh + ((size_t)bh * Nseq + qt * 128 + wid * 16) * 32;
        const uint32_t* qb2 = Ql + ((size_t)bh * Nseq + qt * 128 + wid * 16) * 32;
        #pragma unroll
        for (int ks = 0; ks < 4; ks++) {
            int c0 = ks * 8 + tg;
            qh[ks][0] = qb[g * 32 + c0];        qh[ks][1] = qb[(g + 8) * 32 + c0];
            qh[ks][2] = qb[g * 32 + c0 + 4];    qh[ks][3] = qb[(g + 8) * 32 + c0 + 4];
            ql[ks][0] = qb2[g * 32 + c0];       ql[ks][1] = qb2[(g + 8) * 32 + c0];
            ql[ks][2] = qb2[g * 32 + c0 + 4];   ql[ks][3] = qb2[(g + 8) * 32 + c0 + 4];
        }
    }

    float Oa[8][4];
    #pragma unroll
    for (int i = 0; i < 8; i++)
        #pragma unroll
        for (int j = 0; j < 4; j++) Oa[i][j] = 0.f;
    float mr0 = -1e30f, mr1 = -1e30f, lr0 = 0.f, lr1 = 0.f;

    const uint32_t* kgh = Kh + (size_t)bh * Nseq * 32;
    const uint32_t* vgh = Vh + (size_t)bh * Nseq * 32;

    for (int kt = 0; kt < 8; kt++) {
        __syncthreads();
        #pragma unroll
        for (int i = 0; i < 4; i++) {
            int f = tid + i * 256;
            int key = f >> 3, c = f & 7;
            size_t gidx = ((size_t)(kt * 128 + key)) * 32 + c * 4;
            *(uint4*)(Khs + key * KS_STRIDE + c * 4) = *(const uint4*)(kgh + gidx);
            uint4 wv = *(const uint4*)(vgh + gidx);
            uint32_t wsv[4] = {wv.x, wv.y, wv.z, wv.w};
            #pragma unroll
            for (int s2 = 0; s2 < 4; s2++) {
                int hd0 = c * 8 + s2 * 2;
                Vh16[hd0 * (VS_STRIDE * 2) + key]       = (uint16_t)(wsv[s2] & 0xffff);
                Vh16[(hd0 + 1) * (VS_STRIDE * 2) + key] = (uint16_t)(wsv[s2] >> 16);
            }
        }
        __syncthreads();

        // S = Q K^T, 2 terms, ldmatrix K frags
        float Sf[16][4];
        #pragma unroll
        for (int ni = 0; ni < 16; ni++)
            #pragma unroll
            for (int q = 0; q < 4; q++) Sf[ni][q] = 0.f;
        #pragma unroll
        for (int ks = 0; ks < 4; ks++) {
            uint32_t bhs[16][2];
            #pragma unroll
            for (int p = 0; p < 8; p++) {
                uint32_t t[4];
                ldsm_x4(t, kAddr + p * (16 * KS_STRIDE * 4) + ks * 32);
                bhs[2 * p][0] = t[0]; bhs[2 * p][1] = t[1];
                bhs[2 * p + 1][0] = t[2]; bhs[2 * p + 1][1] = t[3];
            }
            #pragma unroll
            for (int ni = 0; ni < 16; ni++)
                mma_f16(Sf[ni], qh[ks], bhs[ni]);
            #pragma unroll
            for (int ni = 0; ni < 16; ni++)
                mma_f16(Sf[ni], ql[ks], bhs[ni]);
        }

        // online softmax (rows g, g+8)
        float tm0 = -1e30f, tm1 = -1e30f;
        #pragma unroll
        for (int ni = 0; ni < 16; ni++) {
            tm0 = fmaxf(tm0, fmaxf(Sf[ni][0], Sf[ni][1]));
            tm1 = fmaxf(tm1, fmaxf(Sf[ni][2], Sf[ni][3]));
        }
        tm0 = fmaxf(tm0, __shfl_xor_sync(0xffffffffu, tm0, 1));
        tm0 = fmaxf(tm0, __shfl_xor_sync(0xffffffffu, tm0, 2));
        tm1 = fmaxf(tm1, __shfl_xor_sync(0xffffffffu, tm1, 1));
        tm1 = fmaxf(tm1, __shfl_xor_sync(0xffffffffu, tm1, 2));
        float mn0 = fmaxf(mr0, tm0), mn1 = fmaxf(mr1, tm1);
        float al0 = __expf(mr0 - mn0), al1 = __expf(mr1 - mn1);
        mr0 = mn0; mr1 = mn1;
        float s0 = 0.f, s1 = 0.f;
        #pragma unroll
        for (int ni = 0; ni < 16; ni++) {
            Sf[ni][0] = __expf(Sf[ni][0] - mn0);
            Sf[ni][1] = __expf(Sf[ni][1] - mn0);
            Sf[ni][2] = __expf(Sf[ni][2] - mn1);
            Sf[ni][3] = __expf(Sf[ni][3] - mn1);
            s0 += Sf[ni][0] + Sf[ni][1];
            s1 += Sf[ni][2] + Sf[ni][3];
        }
        s0 += __shfl_xor_sync(0xffffffffu, s0, 1);
        s0 += __shfl_xor_sync(0xffffffffu, s0, 2);
        s1 += __shfl_xor_sync(0xffffffffu, s1, 1);
        s1 += __shfl_xor_sync(0xffffffffu, s1, 2);
        lr0 = lr0 * al0 + s0;
        lr1 = lr1 * al1 + s1;
        #pragma unroll
        for (int ni = 0; ni < 8; ni++) {
            Oa[ni][0] *= al0; Oa[ni][1] *= al0;
            Oa[ni][2] *= al1; Oa[ni][3] *= al1;
        }

        // O += P V, 2 terms, ldmatrix V frags
        #pragma unroll
        for (int j = 0; j < 8; j++) {
            uint32_t ph[4], pl[4];
            splitpair_h(Sf[2*j][0],   Sf[2*j][1],   ph[0], pl[0]);
            splitpair_h(Sf[2*j][2],   Sf[2*j][3],   ph[1], pl[1]);
            splitpair_h(Sf[2*j+1][0], Sf[2*j+1][1], ph[2], pl[2]);
            splitpair_h(Sf[2*j+1][2], Sf[2*j+1][3], ph[3], pl[3]);
            uint32_t vf[8][2];
            #pragma unroll
            for (int p = 0; p < 4; p++) {
                uint32_t t[4];
                ldsm_x4(t, vAddr + p * (16 * VS_STRIDE * 4) + j * 32);
                vf[2 * p][0] = t[0]; vf[2 * p][1] = t[1];
                vf[2 * p + 1][0] = t[2]; vf[2 * p + 1][1] = t[3];
            }
            #pragma unroll
            for (int ni = 0; ni < 8; ni++)
                mma_f16(Oa[ni], ph, vf[ni]);
            #pragma unroll
            for (int ni = 0; ni < 8; ni++)
                mma_f16(Oa[ni], pl, vf[ni]);
        }
    }

    // epilogue: Ohi/Olo fp16 split, [m][C] packed u32
    float inv0 = 1.f / lr0, inv1 = 1.f / lr1;
    int b = bh / Hh, h = bh % Hh;
    int nA = qt * 128 + wid * 16 + g;
    int nB = nA + 8;
    #pragma unroll
    for (int ni = 0; ni < 8; ni++) {
        int hd = ni * 8 + tg * 2;
        float2 vA, vB;
        vA.x = Oa[ni][0] * inv0; vA.y = Oa[ni][1] * inv0;
        vB.x = Oa[ni][2] * inv1; vB.y = Oa[ni][3] * inv1;
        size_t iA = (((size_t)b * Nseq + nA) * Cdim + h * HD + hd) >> 1;
        size_t iB = (((size_t)b * Nseq + nB) * Cdim + h * HD + hd) >> 1;
        uint32_t hA, lA, hB, lB;
        splitpair_h(vA.x, vA.y, hA, lA);
        splitpair_h(vB.x, vB.y, hB, lB);
        Ohi[iA] = hA; Olo[iA] = lA;
        Ohi[iB] = hB; Olo[iB] = lB;
    }
}

// ===========================================================================
extern "C" void kernel_launch(void* const* d_in, const int* in_sizes, int n_in,
                              void* d_out, int out_size)
{
    const float* x      = (const float*)d_in[0];
    const float* w_qkv  = (const float*)d_in[1];
    const float* b_qkv  = (const float*)d_in[2];
    const float* w_proj = (const float*)d_in[3];
    const float* b_proj = (const float*)d_in[4];
    const float* q_a = (const float*)d_in[5];
    const float* q_b = (const float*)d_in[6];
    const float* k_a = (const float*)d_in[7];
    const float* k_b = (const float*)d_in[8];
    const float* v_a = (const float*)d_in[9];
    const float* v_b = (const float*)d_in[10];
    const float* o_a = (const float*)d_in[11];
    const float* o_b = (const float*)d_in[12];
    float* out = (float*)d_out;

    void* sym = nullptr;
    cudaGetSymbolAddress(&sym, g_scratch);
    float* base = (float*)sym;
    uint32_t* xhi = (uint32_t*)(base + F_XHI);
    uint32_t* xlo = (uint32_t*)(base + F_XLO);
    uint32_t* wqh = (uint32_t*)(base + F_WQH);
    uint32_t* wph = (uint32_t*)(base + F_WPH);
    uint32_t* Qhp = (uint32_t*)(base + F_QH);
    uint32_t* Qlp = (uint32_t*)(base + F_QL);
    uint32_t* Khp = (uint32_t*)(base + F_KH);
    uint32_t* Vhp = (uint32_t*)(base + F_VH);
    uint32_t* Ohip = (uint32_t*)(base + F_OHI);
    uint32_t* Olop = (uint32_t*)(base + F_OLO);

    cudaFuncSetAttribute(gemm_f16x2_kernel<0>, cudaFuncAttributeMaxDynamicSharedMemorySize, GEMM_SMEM);
    cudaFuncSetAttribute(gemm_f16x2_kernel<1>, cudaFuncAttributeMaxDynamicSharedMemorySize, GEMM_SMEM);
    cudaFuncSetAttribute(attn_mma_kernel, cudaFuncAttributeMaxDynamicSharedMemorySize, ATT_SMEM);

    split_kernel<<<QKV_ELEMS / 1024, 256>>>(x, xhi, xlo);
    weff_kernel<<<3 * Cdim, 128>>>(w_qkv, wqh, q_b, q_a, k_b, k_a, v_b, v_a);
    weff_kernel<<<Cdim, 128>>>(w_proj, wph, o_b, o_a, o_b, o_a, o_b, o_a);

    gemm_f16x2_kernel<0><<<dim3(18, 64), 256, GEMM_SMEM>>>(
        xhi, xlo, wqh, b_qkv, nullptr, Qhp, Qlp, Khp, Vhp);

    attn_mma_kernel<<<dim3(8, Bsz * Hh), 256, ATT_SMEM>>>(
        Qhp, Qlp, Khp, Vhp, Ohip, Olop);

    gemm_f16x2_kernel<1><<<dim3(6, 64), 256, GEMM_SMEM>>>(
        Ohip, Olop, wph, b_proj, out, nullptr, nullptr, nullptr, nullptr);
}

// round 13
// speedup vs baseline: 1.1214x; 1.1214x over previous
#include <cuda_runtime.h>
#include <cuda_fp16.h>
#include <cstdint>

#define Bsz 8
#define Nseq 1024
#define Cdim 768
#define Hh 12
#define HD 64
#define RANK 8
#define SCALE 0.125f
#define Mrows (Bsz * Nseq)          // 8192

#define QKV_ELEMS (Bsz * Hh * Nseq * HD)   // 6291456

// float-slot offsets into g_scratch
#define F_XHI  ((size_t)0)
#define F_XLO  (F_XHI + QKV_ELEMS / 2)
#define F_WQH  (F_XLO + QKV_ELEMS / 2)
#define F_WPH  (F_WQH + (size_t)(3 * Cdim * Cdim) / 2)
#define F_QH   (F_WPH + (size_t)(Cdim * Cdim) / 2)
#define F_QL   (F_QH + QKV_ELEMS / 2)
#define F_KH   (F_QL + QKV_ELEMS / 2)
#define F_VH   (F_KH + QKV_ELEMS / 2)
#define F_OHI  (F_VH + QKV_ELEMS / 2)
#define F_OLO  (F_OHI + QKV_ELEMS / 2)
#define SCRATCH_FLOATS (F_OLO + QKV_ELEMS / 2)

__device__ float g_scratch[SCRATCH_FLOATS];

// ===========================================================================
// helpers
// ===========================================================================
__device__ __forceinline__ uint32_t smem_u32(const void* p) {
    uint32_t a;
    asm("{ .reg .u64 t; cvta.to.shared.u64 t, %1; cvt.u32.u64 %0, t; }" : "=r"(a) : "l"(p));
    return a;
}
__device__ __forceinline__ void cp_async16(uint32_t dst, const void* src) {
    asm volatile("cp.async.cg.shared.global [%0], [%1], 16;" :: "r"(dst), "l"(src) : "memory");
}
__device__ __forceinline__ void ldsm_x4(uint32_t* r, uint32_t addr) {
    asm volatile("ldmatrix.sync.aligned.m8n8.x4.shared.b16 {%0,%1,%2,%3}, [%4];"
        : "=r"(r[0]), "=r"(r[1]), "=r"(r[2]), "=r"(r[3]) : "r"(addr));
}
__device__ __forceinline__ void ldsm_x4_trans(uint32_t* r, uint32_t addr) {
    asm volatile("ldmatrix.sync.aligned.m8n8.x4.trans.shared.b16 {%0,%1,%2,%3}, [%4];"
        : "=r"(r[0]), "=r"(r[1]), "=r"(r[2]), "=r"(r[3]) : "r"(addr));
}
__device__ __forceinline__ void mma_f16(float* c, const uint32_t* a, const uint32_t* b) {
    asm volatile("mma.sync.aligned.m16n8k16.row.col.f32.f16.f16.f32 "
        "{%0,%1,%2,%3}, {%4,%5,%6,%7}, {%8,%9}, {%0,%1,%2,%3};"
        : "+f"(c[0]), "+f"(c[1]), "+f"(c[2]), "+f"(c[3])
        : "r"(a[0]), "r"(a[1]), "r"(a[2]), "r"(a[3]), "r"(b[0]), "r"(b[1]));
}

__device__ __forceinline__ void splitpair_h(float x, float y, uint32_t& hi, uint32_t& lo) {
    __half2 h, l;
    h.x = __float2half_rn(x);
    h.y = __float2half_rn(y);
    l.x = __float2half_rn(x - __half2float(h.x));
    l.y = __float2half_rn(y - __half2float(h.y));
    hi = *reinterpret_cast<uint32_t*>(&h);
    lo = *reinterpret_cast<uint32_t*>(&l);
}
__device__ __forceinline__ uint32_t pack2h(float x, float y) {
    __half2 h;
    h.x = __float2half_rn(x);
    h.y = __float2half_rn(y);
    return *reinterpret_cast<uint32_t*>(&h);
}

// ===========================================================================
// fp16 split (x only)
// ===========================================================================
__global__ void __launch_bounds__(256) split_kernel(
    const float* __restrict__ in, uint32_t* __restrict__ hi,
    uint32_t* __restrict__ lo)
{
    int i = blockIdx.x * 256 + threadIdx.x;
    float4 v = ((const float4*)in)[i];
    uint32_t h0, l0, h1, l1;
    splitpair_h(v.x, v.y, h0, l0);
    splitpair_h(v.z, v.w, h1, l1);
    hi[i * 2]     = h0;
    hi[i * 2 + 1] = h1;
    lo[i * 2]     = l0;
    lo[i * 2 + 1] = l1;
}

// ===========================================================================
// W_eff = W + B*A  (rank-8 update), packed to fp16 hi only.
// ===========================================================================
__global__ void __launch_bounds__(128) weff_kernel(
    const float* __restrict__ w, uint32_t* __restrict__ hi,
    const float* __restrict__ b0, const float* __restrict__ a0,
    const float* __restrict__ b1, const float* __restrict__ a1,
    const float* __restrict__ b2, const float* __restrict__ a2)
{
    int d = blockIdx.x;
    int sec = d / Cdim;
    int dd = d - sec * Cdim;
    const float* bb = (sec == 0) ? b0 : (sec == 1) ? b1 : b2;
    const float* aa = (sec == 0) ? a0 : (sec == 1) ? a1 : a2;
    float bv[8];
    #pragma unroll
    for (int r = 0; r < 8; r++) bv[r] = bb[dd * 8 + r];
    int c0 = threadIdx.x * 6;
    float v[6];
    #pragma unroll
    for (int i = 0; i < 6; i++) v[i] = w[(size_t)d * Cdim + c0 + i];
    #pragma unroll
    for (int r = 0; r < 8; r++) {
        float br = bv[r];
        const float* ar = aa + (size_t)r * Cdim + c0;
        #pragma unroll
        for (int i = 0; i < 6; i++) v[i] += br * ar[i];
    }
    #pragma unroll
    for (int p = 0; p < 3; p++)
        hi[(size_t)d * (Cdim / 2) + (c0 >> 1) + p] = pack2h(v[2 * p], v[2 * p + 1]);
}

// ===========================================================================
// fp16 2-term NT GEMM, 128x128 tile, BK=32, 8 warps, cp.async + ldmatrix,
// 2 CTAs/SM.  (R12 version — measured faster than scalar-LDS)
// ===========================================================================
#define GK768_U32 384
#define SROW 20
#define STAGE_U32 (3 * 128 * SROW)          // Ahi, Alo, Bhi
#define STAGE_BYTES (STAGE_U32 * 4)         // 30720
#define GEMM_SMEM (2 * STAGE_BYTES)         // 61440

template <int MODE>
__global__ void __launch_bounds__(256, 2) gemm_f16x2_kernel(
    const uint32_t* __restrict__ Ahi, const uint32_t* __restrict__ Alo,
    const uint32_t* __restrict__ Bhi,
    const float* __restrict__ bias,
    float* __restrict__ outf,
    uint32_t* __restrict__ Qho, uint32_t* __restrict__ Qlo2,
    uint32_t* __restrict__ Kho, uint32_t* __restrict__ Vho)
{
    extern __shared__ uint32_t sm[];
    uint32_t sbase = smem_u32(sm);
    int tid = threadIdx.x;
    int wid = tid >> 5, lane = tid & 31;
    int wm = wid >> 2, wn = wid & 3;
    int m0 = blockIdx.y * 128, n0 = blockIdx.x * 128;
    int g = lane >> 2, tg = lane & 3;

    float C[4][4][4];
    #pragma unroll
    for (int a = 0; a < 4; a++)
        #pragma unroll
        for (int b = 0; b < 4; b++)
            #pragma unroll
            for (int q = 0; q < 4; q++) C[a][b][q] = 0.f;

    int row_l = tid >> 2, kq_l = tid & 3;
    int row_h = (tid + 256) >> 2;

    uint32_t d0b = (row_l * SROW + kq_l * 4) * 4;
    uint32_t d1b = (row_h * SROW + kq_l * 4) * 4;
    const uint32_t* Asrc0 = Ahi + (size_t)(m0 + row_l) * GK768_U32 + kq_l * 4;
    const uint32_t* Lsrc0 = Alo + (size_t)(m0 + row_l) * GK768_U32 + kq_l * 4;
    const uint32_t* Bsrc0 = Bhi + (size_t)(n0 + row_l) * GK768_U32 + kq_l * 4;
    const uint32_t* Asrc1 = Ahi + (size_t)(m0 + row_h) * GK768_U32 + kq_l * 4;
    const uint32_t* Lsrc1 = Alo + (size_t)(m0 + row_h) * GK768_U32 + kq_l * 4;
    const uint32_t* Bsrc1 = Bhi + (size_t)(n0 + row_h) * GK768_U32 + kq_l * 4;

    // ldmatrix per-lane base addresses (bytes)
    uint32_t aAddr = sbase +
        (uint32_t)((wm * 64 + (lane & 7) + ((lane >> 3) & 1) * 8) * SROW * 4) +
        (uint32_t)((lane >> 4) * 16);
    uint32_t bAddr = sbase + 5120 * 4 +
        (uint32_t)((wn * 32 + (lane & 7) + ((lane & 16) >> 1)) * SROW * 4) +
        (uint32_t)(((lane >> 3) & 1) * 16);

    {
        uint32_t db = sbase;
        cp_async16(db + d0b,                Asrc0);
        cp_async16(db + 2560 * 4 + d0b,     Lsrc0);
        cp_async16(db + 5120 * 4 + d0b,     Bsrc0);
        cp_async16(db + d1b,                Asrc1);
        cp_async16(db + 2560 * 4 + d1b,     Lsrc1);
        cp_async16(db + 5120 * 4 + d1b,     Bsrc1);
        asm volatile("cp.async.commit_group;" ::: "memory");
    }

    for (int c = 0; c < 24; c++) {
        int s = c & 1;
        if (c < 23) {
            uint32_t off = (c + 1) * 16;
            uint32_t db = sbase + (s ^ 1) * STAGE_BYTES;
            cp_async16(db + d0b,            Asrc0 + off);
            cp_async16(db + 2560 * 4 + d0b, Lsrc0 + off);
            cp_async16(db + 5120 * 4 + d0b, Bsrc0 + off);
            cp_async16(db + d1b,            Asrc1 + off);
            cp_async16(db + 2560 * 4 + d1b, Lsrc1 + off);
            cp_async16(db + 5120 * 4 + d1b, Bsrc1 + off);
            asm volatile("cp.async.commit_group;" ::: "memory");
            asm volatile("cp.async.wait_group 1;" ::: "memory");
        } else {
            asm volatile("cp.async.wait_group 0;" ::: "memory");
        }
        __syncthreads();

        uint32_t bufo = (uint32_t)(s * STAGE_BYTES);
        #pragma unroll
        for (int ks = 0; ks < 2; ks++) {
            uint32_t ko = (uint32_t)(ks * 32);
            uint32_t ah[4][4], al[4][4], bh[4][2];
            #pragma unroll
            for (int mi = 0; mi < 4; mi++)
                ldsm_x4(ah[mi], aAddr + bufo + mi * (16 * SROW * 4) + ko);
            #pragma unroll
            for (int mi = 0; mi < 4; mi++)
                ldsm_x4(al[mi], aAddr + bufo + 2560 * 4 + mi * (16 * SROW * 4) + ko);
            #pragma unroll
            for (int p = 0; p < 2; p++) {
                uint32_t t[4];
                ldsm_x4(t, bAddr + bufo + p * (16 * SROW * 4) + ko);
                bh[2 * p][0] = t[0]; bh[2 * p][1] = t[1];
                bh[2 * p + 1][0] = t[2]; bh[2 * p + 1][1] = t[3];
            }
            #pragma unroll
            for (int mi = 0; mi < 4; mi++)
                #pragma unroll
                for (int ni = 0; ni < 4; ni++)
                    mma_f16(C[mi][ni], ah[mi], bh[ni]);
            #pragma unroll
            for (int mi = 0; mi < 4; mi++)
                #pragma unroll
                for (int ni = 0; ni < 4; ni++)
                    mma_f16(C[mi][ni], al[mi], bh[ni]);
        }
        __syncthreads();
    }

    // ------------------------------ epilogue ------------------------------
    int sct = 0, dbase = 0;
    if (MODE == 0) {
        sct = n0 / Cdim;
        dbase = n0 - sct * Cdim;
    }
    #pragma unroll
    for (int mi = 0; mi < 4; mi++) {
        int m_a = m0 + wm * 64 + mi * 16 + g;
        int m_b = m_a + 8;
        int ba = m_a >> 10, na = m_a & 1023;
        int bb = m_b >> 10, nb = m_b & 1023;
        #pragma unroll
        for (int ni = 0; ni < 4; ni++) {
            int dloc = wn * 32 + ni * 8 + tg * 2;
            int d0 = n0 + dloc;
            float2 va, vb2;
            va.x  = C[mi][ni][0] + bias[d0];
            va.y  = C[mi][ni][1] + bias[d0 + 1];
            vb2.x = C[mi][ni][2] + bias[d0];
            vb2.y = C[mi][ni][3] + bias[d0 + 1];
            if (MODE == 0) {
                int dd0 = dbase + dloc;
                int h = dd0 >> 6, hd = dd0 & 63;
                size_t iA = (((size_t)(ba * Hh + h) * Nseq) + na) * 32 + (hd >> 1);
                size_t iB = (((size_t)(bb * Hh + h) * Nseq) + nb) * 32 + (hd >> 1);
                if (sct == 0) {
                    va.x *= SCALE; va.y *= SCALE; vb2.x *= SCALE; vb2.y *= SCALE;
                    uint32_t hA, lA, hB, lB;
                    splitpair_h(va.x, va.y, hA, lA);
                    splitpair_h(vb2.x, vb2.y, hB, lB);
                    Qho[iA] = hA; Qlo2[iA] = lA;
                    Qho[iB] = hB; Qlo2[iB] = lB;
                } else {
                    uint32_t* th = (sct == 1) ? Kho : Vho;
                    th[iA] = pack2h(va.x, va.y);
                    th[iB] = pack2h(vb2.x, vb2.y);
                }
            } else {
                *(float2*)(outf + (size_t)m_a * Cdim + d0) = va;
                *(float2*)(outf + (size_t)m_b * Cdim + d0) = vb2;
            }
        }
    }
}

// ===========================================================================
// Flash attention, fp16 2-term. K AND V both stored row-major in smem
// (stride 36 u32, 16B-aligned rows). K frags via ldmatrix, V frags via
// ldmatrix.trans — NO transpose stores.
// ===========================================================================
#define KST 36
#define ATT_SMEM_U32 (2 * 128 * KST)       // 9216
#define ATT_SMEM (ATT_SMEM_U32 * 4)        // 36864

__global__ void __launch_bounds__(256) attn_mma_kernel(
    const uint32_t* __restrict__ Qh, const uint32_t* __restrict__ Ql,
    const uint32_t* __restrict__ Kh, const uint32_t* __restrict__ Vh,
    uint32_t* __restrict__ Ohi, uint32_t* __restrict__ Olo)
{
    extern __shared__ uint32_t sm[];
    uint32_t* Khs = sm;                    // 128 x 36
    uint32_t* Vhs = sm + 128 * KST;        // 128 x 36 (row-major, same as K)

    int bh = blockIdx.y, qt = blockIdx.x;
    int tid = threadIdx.x, wid = tid >> 5, lane = tid & 31;
    int g = lane >> 2, tg = lane & 3;

    // K: non-trans B-pattern lane address
    uint32_t kAddr = smem_u32(Khs) +
        (uint32_t)(((lane & 7) + ((lane & 16) >> 1)) * KST * 4) +
        (uint32_t)(((lane >> 3) & 1) * 16);
    // V: trans pattern lane address (rows = keys, cols = hd)
    uint32_t vAddr = smem_u32(Vhs) +
        (uint32_t)((lane & 15) * KST * 4) +
        (uint32_t)((lane >> 4) * 16);

    uint32_t qh[4][4], ql[4][4];
    {
        const uint32_t* qb  = Qh + ((size_t)bh * Nseq + qt * 128 + wid * 16) * 32;
        const uint32_t* qb2 = Ql + ((size_t)bh * Nseq + qt * 128 + wid * 16) * 32;
        #pragma unroll
        for (int ks = 0; ks < 4; ks++) {
            int c0 = ks * 8 + tg;
            qh[ks][0] = qb[g * 32 + c0];        qh[ks][1] = qb[(g + 8) * 32 + c0];
            qh[ks][2] = qb[g * 32 + c0 + 4];    qh[ks][3] = qb[(g + 8) * 32 + c0 + 4];
            ql[ks][0] = qb2[g * 32 + c0];       ql[ks][1] = qb2[(g + 8) * 32 + c0];
            ql[ks][2] = qb2[g * 32 + c0 + 4];   ql[ks][3] = qb2[(g + 8) * 32 + c0 + 4];
        }
    }

    float Oa[8][4];
    #pragma unroll
    for (int i = 0; i < 8; i++)
        #pragma unroll
        for (int j = 0; j < 4; j++) Oa[i][j] = 0.f;
    float mr0 = -1e30f, mr1 = -1e30f, lr0 = 0.f, lr1 = 0.f;

    const uint32_t* kgh = Kh + (size_t)bh * Nseq * 32;
    const uint32_t* vgh = Vh + (size_t)bh * Nseq * 32;

    for (int kt = 0; kt < 8; kt++) {
        __syncthreads();
        #pragma unroll
        for (int i = 0; i < 4; i++) {
            int f = tid + i * 256;
            int key = f >> 3, c = f & 7;
            size_t gidx = ((size_t)(kt * 128 + key)) * 32 + c * 4;
            *(uint4*)(Khs + key * KST + c * 4) = *(const uint4*)(kgh + gidx);
            *(uint4*)(Vhs + key * KST + c * 4) = *(const uint4*)(vgh + gidx);
        }
        __syncthreads();

        // S = Q K^T, 2 terms, ldmatrix K frags
        float Sf[16][4];
        #pragma unroll
        for (int ni = 0; ni < 16; ni++)
            #pragma unroll
            for (int q = 0; q < 4; q++) Sf[ni][q] = 0.f;
        #pragma unroll
        for (int ks = 0; ks < 4; ks++) {
            uint32_t bhs[16][2];
            #pragma unroll
            for (int p = 0; p < 8; p++) {
                uint32_t t[4];
                ldsm_x4(t, kAddr + p * (16 * KST * 4) + ks * 32);
                bhs[2 * p][0] = t[0]; bhs[2 * p][1] = t[1];
                bhs[2 * p + 1][0] = t[2]; bhs[2 * p + 1][1] = t[3];
            }
            #pragma unroll
            for (int ni = 0; ni < 16; ni++)
                mma_f16(Sf[ni], qh[ks], bhs[ni]);
            #pragma unroll
            for (int ni = 0; ni < 16; ni++)
                mma_f16(Sf[ni], ql[ks], bhs[ni]);
        }

        // online softmax (rows g, g+8)
        float tm0 = -1e30f, tm1 = -1e30f;
        #pragma unroll
        for (int ni = 0; ni < 16; ni++) {
            tm0 = fmaxf(tm0, fmaxf(Sf[ni][0], Sf[ni][1]));
            tm1 = fmaxf(tm1, fmaxf(Sf[ni][2], Sf[ni][3]));
        }
        tm0 = fmaxf(tm0, __shfl_xor_sync(0xffffffffu, tm0, 1));
        tm0 = fmaxf(tm0, __shfl_xor_sync(0xffffffffu, tm0, 2));
        tm1 = fmaxf(tm1, __shfl_xor_sync(0xffffffffu, tm1, 1));
        tm1 = fmaxf(tm1, __shfl_xor_sync(0xffffffffu, tm1, 2));
        float mn0 = fmaxf(mr0, tm0), mn1 = fmaxf(mr1, tm1);
        float al0 = __expf(mr0 - mn0), al1 = __expf(mr1 - mn1);
        mr0 = mn0; mr1 = mn1;
        float s0 = 0.f, s1 = 0.f;
        #pragma unroll
        for (int ni = 0; ni < 16; ni++) {
            Sf[ni][0] = __expf(Sf[ni][0] - mn0);
            Sf[ni][1] = __expf(Sf[ni][1] - mn0);
            Sf[ni][2] = __expf(Sf[ni][2] - mn1);
            Sf[ni][3] = __expf(Sf[ni][3] - mn1);
            s0 += Sf[ni][0] + Sf[ni][1];
            s1 += Sf[ni][2] + Sf[ni][3];
        }
        s0 += __shfl_xor_sync(0xffffffffu, s0, 1);
        s0 += __shfl_xor_sync(0xffffffffu, s0, 2);
        s1 += __shfl_xor_sync(0xffffffffu, s1, 1);
        s1 += __shfl_xor_sync(0xffffffffu, s1, 2);
        lr0 = lr0 * al0 + s0;
        lr1 = lr1 * al1 + s1;
        #pragma unroll
        for (int ni = 0; ni < 8; ni++) {
            Oa[ni][0] *= al0; Oa[ni][1] *= al0;
            Oa[ni][2] *= al1; Oa[ni][3] *= al1;
        }

        // O += P V, 2 terms, ldmatrix.trans V frags (row-major V in smem)
        #pragma unroll
        for (int j = 0; j < 8; j++) {
            uint32_t ph[4], pl[4];
            splitpair_h(Sf[2*j][0],   Sf[2*j][1],   ph[0], pl[0]);
            splitpair_h(Sf[2*j][2],   Sf[2*j][3],   ph[1], pl[1]);
            splitpair_h(Sf[2*j+1][0], Sf[2*j+1][1], ph[2], pl[2]);
            splitpair_h(Sf[2*j+1][2], Sf[2*j+1][3], ph[3], pl[3]);
            uint32_t vf[8][2];
            #pragma unroll
            for (int p = 0; p < 4; p++) {
                uint32_t t[4];
                ldsm_x4_trans(t, vAddr + j * (16 * KST * 4) + p * 32);
                vf[2 * p][0] = t[0]; vf[2 * p][1] = t[1];
                vf[2 * p + 1][0] = t[2]; vf[2 * p + 1][1] = t[3];
            }
            #pragma unroll
            for (int ni = 0; ni < 8; ni++)
                mma_f16(Oa[ni], ph, vf[ni]);
            #pragma unroll
            for (int ni = 0; ni < 8; ni++)
                mma_f16(Oa[ni], pl, vf[ni]);
        }
    }

    // epilogue: Ohi/Olo fp16 split, [m][C] packed u32
    float inv0 = 1.f / lr0, inv1 = 1.f / lr1;
    int b = bh / Hh, h = bh % Hh;
    int nA = qt * 128 + wid * 16 + g;
    int nB = nA + 8;
    #pragma unroll
    for (int ni = 0; ni < 8; ni++) {
        int hd = ni * 8 + tg * 2;
        float2 vA, vB;
        vA.x = Oa[ni][0] * inv0; vA.y = Oa[ni][1] * inv0;
        vB.x = Oa[ni][2] * inv1; vB.y = Oa[ni][3] * inv1;
        size_t iA = (((size_t)b * Nseq + nA) * Cdim + h * HD + hd) >> 1;
        size_t iB = (((size_t)b * Nseq + nB) * Cdim + h * HD + hd) >> 1;
        uint32_t hA, lA, hB, lB;
        splitpair_h(vA.x, vA.y, hA, lA);
        splitpair_h(vB.x, vB.y, hB, lB);
        Ohi[iA] = hA; Olo[iA] = lA;
        Ohi[iB] = hB; Olo[iB] = lB;
    }
}

// ===========================================================================
extern "C" void kernel_launch(void* const* d_in, const int* in_sizes, int n_in,
                              void* d_out, int out_size)
{
    const float* x      = (const float*)d_in[0];
    const float* w_qkv  = (const float*)d_in[1];
    const float* b_qkv  = (const float*)d_in[2];
    const float* w_proj = (const float*)d_in[3];
    const float* b_proj = (const float*)d_in[4];
    const float* q_a = (const float*)d_in[5];
    const float* q_b = (const float*)d_in[6];
    const float* k_a = (const float*)d_in[7];
    const float* k_b = (const float*)d_in[8];
    const float* v_a = (const float*)d_in[9];
    const float* v_b = (const float*)d_in[10];
    const float* o_a = (const float*)d_in[11];
    const float* o_b = (const float*)d_in[12];
    float* out = (float*)d_out;

    void* sym = nullptr;
    cudaGetSymbolAddress(&sym, g_scratch);
    float* base = (float*)sym;
    uint32_t* xhi = (uint32_t*)(base + F_XHI);
    uint32_t* xlo = (uint32_t*)(base + F_XLO);
    uint32_t* wqh = (uint32_t*)(base + F_WQH);
    uint32_t* wph = (uint32_t*)(base + F_WPH);
    uint32_t* Qhp = (uint32_t*)(base + F_QH);
    uint32_t* Qlp = (uint32_t*)(base + F_QL);
    uint32_t* Khp = (uint32_t*)(base + F_KH);
    uint32_t* Vhp = (uint32_t*)(base + F_VH);
    uint32_t* Ohip = (uint32_t*)(base + F_OHI);
    uint32_t* Olop = (uint32_t*)(base + F_OLO);

    cudaFuncSetAttribute(gemm_f16x2_kernel<0>, cudaFuncAttributeMaxDynamicSharedMemorySize, GEMM_SMEM);
    cudaFuncSetAttribute(gemm_f16x2_kernel<1>, cudaFuncAttributeMaxDynamicSharedMemorySize, GEMM_SMEM);
    cudaFuncSetAttribute(attn_mma_kernel, cudaFuncAttributeMaxDynamicSharedMemorySize, ATT_SMEM);

    split_kernel<<<QKV_ELEMS / 1024, 256>>>(x, xhi, xlo);
    weff_kernel<<<3 * Cdim, 128>>>(w_qkv, wqh, q_b, q_a, k_b, k_a, v_b, v_a);
    weff_kernel<<<Cdim, 128>>>(w_proj, wph, o_b, o_a, o_b, o_a, o_b, o_a);

    gemm_f16x2_kernel<0><<<dim3(18, 64), 256, GEMM_SMEM>>>(
        xhi, xlo, wqh, b_qkv, nullptr, Qhp, Qlp, Khp, Vhp);

    attn_mma_kernel<<<dim3(8, Bsz * Hh), 256, ATT_SMEM>>>(
        Qhp, Qlp, Khp, Vhp, Ohip, Olop);

    gemm_f16x2_kernel<1><<<dim3(6, 64), 256, GEMM_SMEM>>>(
        Ohip, Olop, wph, b_proj, out, nullptr, nullptr, nullptr, nullptr);
}

// round 14
// speedup vs baseline: 1.1314x; 1.0089x over previous
#include <cuda_runtime.h>
#include <cuda_fp16.h>
#include <cstdint>

#define Bsz 8
#define Nseq 1024
#define Cdim 768
#define Hh 12
#define HD 64
#define RANK 8
#define SCALE 0.125f
#define Mrows (Bsz * Nseq)          // 8192

#define QKV_ELEMS (Bsz * Hh * Nseq * HD)   // 6291456

// float-slot offsets into g_scratch
#define F_XHI  ((size_t)0)
#define F_XLO  (F_XHI + QKV_ELEMS / 2)
#define F_WQH  (F_XLO + QKV_ELEMS / 2)
#define F_WPH  (F_WQH + (size_t)(3 * Cdim * Cdim) / 2)
#define F_QH   (F_WPH + (size_t)(Cdim * Cdim) / 2)
#define F_QL   (F_QH + QKV_ELEMS / 2)
#define F_KH   (F_QL + QKV_ELEMS / 2)
#define F_VH   (F_KH + QKV_ELEMS / 2)
#define F_OHI  (F_VH + QKV_ELEMS / 2)
#define F_OLO  (F_OHI + QKV_ELEMS / 2)
#define SCRATCH_FLOATS (F_OLO + QKV_ELEMS / 2)

__device__ float g_scratch[SCRATCH_FLOATS];

// ===========================================================================
// helpers
// ===========================================================================
__device__ __forceinline__ uint32_t smem_u32(const void* p) {
    uint32_t a;
    asm("{ .reg .u64 t; cvta.to.shared.u64 t, %1; cvt.u32.u64 %0, t; }" : "=r"(a) : "l"(p));
    return a;
}
__device__ __forceinline__ void cp_async16(uint32_t dst, const void* src) {
    asm volatile("cp.async.cg.shared.global [%0], [%1], 16;" :: "r"(dst), "l"(src) : "memory");
}
__device__ __forceinline__ void ldsm_x4(uint32_t* r, uint32_t addr) {
    asm volatile("ldmatrix.sync.aligned.m8n8.x4.shared.b16 {%0,%1,%2,%3}, [%4];"
        : "=r"(r[0]), "=r"(r[1]), "=r"(r[2]), "=r"(r[3]) : "r"(addr));
}
__device__ __forceinline__ void ldsm_x4_trans(uint32_t* r, uint32_t addr) {
    asm volatile("ldmatrix.sync.aligned.m8n8.x4.trans.shared.b16 {%0,%1,%2,%3}, [%4];"
        : "=r"(r[0]), "=r"(r[1]), "=r"(r[2]), "=r"(r[3]) : "r"(addr));
}
__device__ __forceinline__ void mma_f16(float* c, const uint32_t* a, const uint32_t* b) {
    asm volatile("mma.sync.aligned.m16n8k16.row.col.f32.f16.f16.f32 "
        "{%0,%1,%2,%3}, {%4,%5,%6,%7}, {%8,%9}, {%0,%1,%2,%3};"
        : "+f"(c[0]), "+f"(c[1]), "+f"(c[2]), "+f"(c[3])
        : "r"(a[0]), "r"(a[1]), "r"(a[2]), "r"(a[3]), "r"(b[0]), "r"(b[1]));
}

__device__ __forceinline__ void splitpair_h(float x, float y, uint32_t& hi, uint32_t& lo) {
    __half2 h, l;
    h.x = __float2half_rn(x);
    h.y = __float2half_rn(y);
    l.x = __float2half_rn(x - __half2float(h.x));
    l.y = __float2half_rn(y - __half2float(h.y));
    hi = *reinterpret_cast<uint32_t*>(&h);
    lo = *reinterpret_cast<uint32_t*>(&l);
}
__device__ __forceinline__ uint32_t pack2h(float x, float y) {
    __half2 h;
    h.x = __float2half_rn(x);
    h.y = __float2half_rn(y);
    return *reinterpret_cast<uint32_t*>(&h);
}

// ===========================================================================
// fp16 split (x only)
// ===========================================================================
__global__ void __launch_bounds__(256) split_kernel(
    const float* __restrict__ in, uint32_t* __restrict__ hi,
    uint32_t* __restrict__ lo)
{
    int i = blockIdx.x * 256 + threadIdx.x;
    float4 v = ((const float4*)in)[i];
    uint32_t h0, l0, h1, l1;
    splitpair_h(v.x, v.y, h0, l0);
    splitpair_h(v.z, v.w, h1, l1);
    hi[i * 2]     = h0;
    hi[i * 2 + 1] = h1;
    lo[i * 2]     = l0;
    lo[i * 2 + 1] = l1;
}

// ===========================================================================
// W_eff = W + B*A  (rank-8 update), packed to fp16 hi only.
// ===========================================================================
__global__ void __launch_bounds__(128) weff_kernel(
    const float* __restrict__ w, uint32_t* __restrict__ hi,
    const float* __restrict__ b0, const float* __restrict__ a0,
    const float* __restrict__ b1, const float* __restrict__ a1,
    const float* __restrict__ b2, const float* __restrict__ a2)
{
    int d = blockIdx.x;
    int sec = d / Cdim;
    int dd = d - sec * Cdim;
    const float* bb = (sec == 0) ? b0 : (sec == 1) ? b1 : b2;
    const float* aa = (sec == 0) ? a0 : (sec == 1) ? a1 : a2;
    float bv[8];
    #pragma unroll
    for (int r = 0; r < 8; r++) bv[r] = bb[dd * 8 + r];
    int c0 = threadIdx.x * 6;
    float v[6];
    #pragma unroll
    for (int i = 0; i < 6; i++) v[i] = w[(size_t)d * Cdim + c0 + i];
    #pragma unroll
    for (int r = 0; r < 8; r++) {
        float br = bv[r];
        const float* ar = aa + (size_t)r * Cdim + c0;
        #pragma unroll
        for (int i = 0; i < 6; i++) v[i] += br * ar[i];
    }
    #pragma unroll
    for (int p = 0; p < 3; p++)
        hi[(size_t)d * (Cdim / 2) + (c0 >> 1) + p] = pack2h(v[2 * p], v[2 * p + 1]);
}

// ===========================================================================
// fp16 2-term NT GEMM, 128x128 tile, BK=32, 8 warps, 3-stage cp.async
// pipeline (ONE barrier per chunk), ldmatrix frag loads, 2 CTAs/SM.
// ===========================================================================
#define GK768_U32 384
#define SROW 20
#define STAGE_U32 (3 * 128 * SROW)          // Ahi, Alo, Bhi
#define STAGE_BYTES (STAGE_U32 * 4)         // 30720
#define NSTAGE 3
#define GEMM_SMEM (NSTAGE * STAGE_BYTES)    // 92160

template <int MODE>
__global__ void __launch_bounds__(256, 2) gemm_f16x2_kernel(
    const uint32_t* __restrict__ Ahi, const uint32_t* __restrict__ Alo,
    const uint32_t* __restrict__ Bhi,
    const float* __restrict__ bias,
    float* __restrict__ outf,
    uint32_t* __restrict__ Qho, uint32_t* __restrict__ Qlo2,
    uint32_t* __restrict__ Kho, uint32_t* __restrict__ Vho)
{
    extern __shared__ uint32_t sm[];
    uint32_t sbase = smem_u32(sm);
    int tid = threadIdx.x;
    int wid = tid >> 5, lane = tid & 31;
    int wm = wid >> 2, wn = wid & 3;
    int m0 = blockIdx.y * 128, n0 = blockIdx.x * 128;
    int g = lane >> 2, tg = lane & 3;

    float C[4][4][4];
    #pragma unroll
    for (int a = 0; a < 4; a++)
        #pragma unroll
        for (int b = 0; b < 4; b++)
            #pragma unroll
            for (int q = 0; q < 4; q++) C[a][b][q] = 0.f;

    int row_l = tid >> 2, kq_l = tid & 3;
    int row_h = (tid + 256) >> 2;

    uint32_t d0b = (row_l * SROW + kq_l * 4) * 4;
    uint32_t d1b = (row_h * SROW + kq_l * 4) * 4;
    const uint32_t* Asrc0 = Ahi + (size_t)(m0 + row_l) * GK768_U32 + kq_l * 4;
    const uint32_t* Lsrc0 = Alo + (size_t)(m0 + row_l) * GK768_U32 + kq_l * 4;
    const uint32_t* Bsrc0 = Bhi + (size_t)(n0 + row_l) * GK768_U32 + kq_l * 4;
    const uint32_t* Asrc1 = Ahi + (size_t)(m0 + row_h) * GK768_U32 + kq_l * 4;
    const uint32_t* Lsrc1 = Alo + (size_t)(m0 + row_h) * GK768_U32 + kq_l * 4;
    const uint32_t* Bsrc1 = Bhi + (size_t)(n0 + row_h) * GK768_U32 + kq_l * 4;

    // ldmatrix per-lane base addresses (bytes)
    uint32_t aAddr = sbase +
        (uint32_t)((wm * 64 + (lane & 7) + ((lane >> 3) & 1) * 8) * SROW * 4) +
        (uint32_t)((lane >> 4) * 16);
    uint32_t bAddr = sbase + 5120 * 4 +
        (uint32_t)((wn * 32 + (lane & 7) + ((lane & 16) >> 1)) * SROW * 4) +
        (uint32_t)(((lane >> 3) & 1) * 16);

    // prologue: chunks 0, 1
    #pragma unroll
    for (int pc = 0; pc < 2; pc++) {
        uint32_t off = pc * 16;
        uint32_t db = sbase + pc * STAGE_BYTES;
        cp_async16(db + d0b,            Asrc0 + off);
        cp_async16(db + 2560 * 4 + d0b, Lsrc0 + off);
        cp_async16(db + 5120 * 4 + d0b, Bsrc0 + off);
        cp_async16(db + d1b,            Asrc1 + off);
        cp_async16(db + 2560 * 4 + d1b, Lsrc1 + off);
        cp_async16(db + 5120 * 4 + d1b, Bsrc1 + off);
        asm volatile("cp.async.commit_group;" ::: "memory");
    }

    int s = 0;
    for (int c = 0; c < 24; c++) {
        if (c < 23)
            asm volatile("cp.async.wait_group 1;" ::: "memory");
        else
            asm volatile("cp.async.wait_group 0;" ::: "memory");
        __syncthreads();

        // issue copy for chunk c+2 (buffer consumed at chunk c-1; safe after sync)
        if (c + 2 < 24) {
            uint32_t off = (c + 2) * 16;
            int sn = s + 2 - ((s + 2 >= NSTAGE) ? NSTAGE : 0);
            uint32_t db = sbase + sn * STAGE_BYTES;
            cp_async16(db + d0b,            Asrc0 + off);
            cp_async16(db + 2560 * 4 + d0b, Lsrc0 + off);
            cp_async16(db + 5120 * 4 + d0b, Bsrc0 + off);
            cp_async16(db + d1b,            Asrc1 + off);
            cp_async16(db + 2560 * 4 + d1b, Lsrc1 + off);
            cp_async16(db + 5120 * 4 + d1b, Bsrc1 + off);
            asm volatile("cp.async.commit_group;" ::: "memory");
        }

        uint32_t bufo = (uint32_t)(s * STAGE_BYTES);
        #pragma unroll
        for (int ks = 0; ks < 2; ks++) {
            uint32_t ko = (uint32_t)(ks * 32);
            uint32_t ah[4][4], al[4][4], bh[4][2];
            #pragma unroll
            for (int mi = 0; mi < 4; mi++)
                ldsm_x4(ah[mi], aAddr + bufo + mi * (16 * SROW * 4) + ko);
            #pragma unroll
            for (int mi = 0; mi < 4; mi++)
                ldsm_x4(al[mi], aAddr + bufo + 2560 * 4 + mi * (16 * SROW * 4) + ko);
            #pragma unroll
            for (int p = 0; p < 2; p++) {
                uint32_t t[4];
                ldsm_x4(t, bAddr + bufo + p * (16 * SROW * 4) + ko);
                bh[2 * p][0] = t[0]; bh[2 * p][1] = t[1];
                bh[2 * p + 1][0] = t[2]; bh[2 * p + 1][1] = t[3];
            }
            #pragma unroll
            for (int mi = 0; mi < 4; mi++)
                #pragma unroll
                for (int ni = 0; ni < 4; ni++)
                    mma_f16(C[mi][ni], ah[mi], bh[ni]);
            #pragma unroll
            for (int mi = 0; mi < 4; mi++)
                #pragma unroll
                for (int ni = 0; ni < 4; ni++)
                    mma_f16(C[mi][ni], al[mi], bh[ni]);
        }
        s = (s + 1 == NSTAGE) ? 0 : s + 1;
    }

    // ------------------------------ epilogue ------------------------------
    int sct = 0, dbase = 0;
    if (MODE == 0) {
        sct = n0 / Cdim;
        dbase = n0 - sct * Cdim;
    }
    #pragma unroll
    for (int mi = 0; mi < 4; mi++) {
        int m_a = m0 + wm * 64 + mi * 16 + g;
        int m_b = m_a + 8;
        int ba = m_a >> 10, na = m_a & 1023;
        int bb = m_b >> 10, nb = m_b & 1023;
        #pragma unroll
        for (int ni = 0; ni < 4; ni++) {
            int dloc = wn * 32 + ni * 8 + tg * 2;
            int d0 = n0 + dloc;
            float2 va, vb2;
            va.x  = C[mi][ni][0] + bias[d0];
            va.y  = C[mi][ni][1] + bias[d0 + 1];
            vb2.x = C[mi][ni][2] + bias[d0];
            vb2.y = C[mi][ni][3] + bias[d0 + 1];
            if (MODE == 0) {
                int dd0 = dbase + dloc;
                int h = dd0 >> 6, hd = dd0 & 63;
                size_t iA = (((size_t)(ba * Hh + h) * Nseq) + na) * 32 + (hd >> 1);
                size_t iB = (((size_t)(bb * Hh + h) * Nseq) + nb) * 32 + (hd >> 1);
                if (sct == 0) {
                    va.x *= SCALE; va.y *= SCALE; vb2.x *= SCALE; vb2.y *= SCALE;
                    uint32_t hA, lA, hB, lB;
                    splitpair_h(va.x, va.y, hA, lA);
                    splitpair_h(vb2.x, vb2.y, hB, lB);
                    Qho[iA] = hA; Qlo2[iA] = lA;
                    Qho[iB] = hB; Qlo2[iB] = lB;
                } else {
                    uint32_t* th = (sct == 1) ? Kho : Vho;
                    th[iA] = pack2h(va.x, va.y);
                    th[iB] = pack2h(vb2.x, vb2.y);
                }
            } else {
                *(float2*)(outf + (size_t)m_a * Cdim + d0) = va;
                *(float2*)(outf + (size_t)m_b * Cdim + d0) = vb2;
            }
        }
    }
}

// ===========================================================================
// Flash attention (R13 version — K/V row-major, ldmatrix + ldmatrix.trans)
// ===========================================================================
#define KST 36
#define ATT_SMEM_U32 (2 * 128 * KST)       // 9216
#define ATT_SMEM (ATT_SMEM_U32 * 4)        // 36864

__global__ void __launch_bounds__(256) attn_mma_kernel(
    const uint32_t* __restrict__ Qh, const uint32_t* __restrict__ Ql,
    const uint32_t* __restrict__ Kh, const uint32_t* __restrict__ Vh,
    uint32_t* __restrict__ Ohi, uint32_t* __restrict__ Olo)
{
    extern __shared__ uint32_t sm[];
    uint32_t* Khs = sm;                    // 128 x 36
    uint32_t* Vhs = sm + 128 * KST;        // 128 x 36 (row-major)

    int bh = blockIdx.y, qt = blockIdx.x;
    int tid = threadIdx.x, wid = tid >> 5, lane = tid & 31;
    int g = lane >> 2, tg = lane & 3;

    uint32_t kAddr = smem_u32(Khs) +
        (uint32_t)(((lane & 7) + ((lane & 16) >> 1)) * KST * 4) +
        (uint32_t)(((lane >> 3) & 1) * 16);
    uint32_t vAddr = smem_u32(Vhs) +
        (uint32_t)((lane & 15) * KST * 4) +
        (uint32_t)((lane >> 4) * 16);

    uint32_t qh[4][4], ql[4][4];
    {
        const uint32_t* qb  = Qh + ((size_t)bh * Nseq + qt * 128 + wid * 16) * 32;
        const uint32_t* qb2 = Ql + ((size_t)bh * Nseq + qt * 128 + wid * 16) * 32;
        #pragma unroll
        for (int ks = 0; ks < 4; ks++) {
            int c0 = ks * 8 + tg;
            qh[ks][0] = qb[g * 32 + c0];        qh[ks][1] = qb[(g + 8) * 32 + c0];
            qh[ks][2] = qb[g * 32 + c0 + 4];    qh[ks][3] = qb[(g + 8) * 32 + c0 + 4];
            ql[ks][0] = qb2[g * 32 + c0];       ql[ks][1] = qb2[(g + 8) * 32 + c0];
            ql[ks][2] = qb2[g * 32 + c0 + 4];   ql[ks][3] = qb2[(g + 8) * 32 + c0 + 4];
        }
    }

    float Oa[8][4];
    #pragma unroll
    for (int i = 0; i < 8; i++)
        #pragma unroll
        for (int j = 0; j < 4; j++) Oa[i][j] = 0.f;
    float mr0 = -1e30f, mr1 = -1e30f, lr0 = 0.f, lr1 = 0.f;

    const uint32_t* kgh = Kh + (size_t)bh * Nseq * 32;
    const uint32_t* vgh = Vh + (size_t)bh * Nseq * 32;

    for (int kt = 0; kt < 8; kt++) {
        __syncthreads();
        #pragma unroll
        for (int i = 0; i < 4; i++) {
            int f = tid + i * 256;
            int key = f >> 3, c = f & 7;
            size_t gidx = ((size_t)(kt * 128 + key)) * 32 + c * 4;
            *(uint4*)(Khs + key * KST + c * 4) = *(const uint4*)(kgh + gidx);
            *(uint4*)(Vhs + key * KST + c * 4) = *(const uint4*)(vgh + gidx);
        }
        __syncthreads();

        float Sf[16][4];
        #pragma unroll
        for (int ni = 0; ni < 16; ni++)
            #pragma unroll
            for (int q = 0; q < 4; q++) Sf[ni][q] = 0.f;
        #pragma unroll
        for (int ks = 0; ks < 4; ks++) {
            uint32_t bhs[16][2];
            #pragma unroll
            for (int p = 0; p < 8; p++) {
                uint32_t t[4];
                ldsm_x4(t, kAddr + p * (16 * KST * 4) + ks * 32);
                bhs[2 * p][0] = t[0]; bhs[2 * p][1] = t[1];
                bhs[2 * p + 1][0] = t[2]; bhs[2 * p + 1][1] = t[3];
            }
            #pragma unroll
            for (int ni = 0; ni < 16; ni++)
                mma_f16(Sf[ni], qh[ks], bhs[ni]);
            #pragma unroll
            for (int ni = 0; ni < 16; ni++)
                mma_f16(Sf[ni], ql[ks], bhs[ni]);
        }

        float tm0 = -1e30f, tm1 = -1e30f;
        #pragma unroll
        for (int ni = 0; ni < 16; ni++) {
            tm0 = fmaxf(tm0, fmaxf(Sf[ni][0], Sf[ni][1]));
            tm1 = fmaxf(tm1, fmaxf(Sf[ni][2], Sf[ni][3]));
        }
        tm0 = fmaxf(tm0, __shfl_xor_sync(0xffffffffu, tm0, 1));
        tm0 = fmaxf(tm0, __shfl_xor_sync(0xffffffffu, tm0, 2));
        tm1 = fmaxf(tm1, __shfl_xor_sync(0xffffffffu, tm1, 1));
        tm1 = fmaxf(tm1, __shfl_xor_sync(0xffffffffu, tm1, 2));
        float mn0 = fmaxf(mr0, tm0), mn1 = fmaxf(mr1, tm1);
        float al0 = __expf(mr0 - mn0), al1 = __expf(mr1 - mn1);
        mr0 = mn0; mr1 = mn1;
        float s0 = 0.f, s1 = 0.f;
        #pragma unroll
        for (int ni = 0; ni < 16; ni++) {
            Sf[ni][0] = __expf(Sf[ni][0] - mn0);
            Sf[ni][1] = __expf(Sf[ni][1] - mn0);
            Sf[ni][2] = __expf(Sf[ni][2] - mn1);
            Sf[ni][3] = __expf(Sf[ni][3] - mn1);
            s0 += Sf[ni][0] + Sf[ni][1];
            s1 += Sf[ni][2] + Sf[ni][3];
        }
        s0 += __shfl_xor_sync(0xffffffffu, s0, 1);
        s0 += __shfl_xor_sync(0xffffffffu, s0, 2);
        s1 += __shfl_xor_sync(0xffffffffu, s1, 1);
        s1 += __shfl_xor_sync(0xffffffffu, s1, 2);
        lr0 = lr0 * al0 + s0;
        lr1 = lr1 * al1 + s1;
        #pragma unroll
        for (int ni = 0; ni < 8; ni++) {
            Oa[ni][0] *= al0; Oa[ni][1] *= al0;
            Oa[ni][2] *= al1; Oa[ni][3] *= al1;
        }

        #pragma unroll
        for (int j = 0; j < 8; j++) {
            uint32_t ph[4], pl[4];
            splitpair_h(Sf[2*j][0],   Sf[2*j][1],   ph[0], pl[0]);
            splitpair_h(Sf[2*j][2],   Sf[2*j][3],   ph[1], pl[1]);
            splitpair_h(Sf[2*j+1][0], Sf[2*j+1][1], ph[2], pl[2]);
            splitpair_h(Sf[2*j+1][2], Sf[2*j+1][3], ph[3], pl[3]);
            uint32_t vf[8][2];
            #pragma unroll
            for (int p = 0; p < 4; p++) {
                uint32_t t[4];
                ldsm_x4_trans(t, vAddr + j * (16 * KST * 4) + p * 32);
                vf[2 * p][0] = t[0]; vf[2 * p][1] = t[1];
                vf[2 * p + 1][0] = t[2]; vf[2 * p + 1][1] = t[3];
            }
            #pragma unroll
            for (int ni = 0; ni < 8; ni++)
                mma_f16(Oa[ni], ph, vf[ni]);
            #pragma unroll
            for (int ni = 0; ni < 8; ni++)
                mma_f16(Oa[ni], pl, vf[ni]);
        }
    }

    float inv0 = 1.f / lr0, inv1 = 1.f / lr1;
    int b = bh / Hh, h = bh % Hh;
    int nA = qt * 128 + wid * 16 + g;
    int nB = nA + 8;
    #pragma unroll
    for (int ni = 0; ni < 8; ni++) {
        int hd = ni * 8 + tg * 2;
        float2 vA, vB;
        vA.x = Oa[ni][0] * inv0; vA.y = Oa[ni][1] * inv0;
        vB.x = Oa[ni][2] * inv1; vB.y = Oa[ni][3] * inv1;
        size_t iA = (((size_t)b * Nseq + nA) * Cdim + h * HD + hd) >> 1;
        size_t iB = (((size_t)b * Nseq + nB) * Cdim + h * HD + hd) >> 1;
        uint32_t hA, lA, hB, lB;
        splitpair_h(vA.x, vA.y, hA, lA);
        splitpair_h(vB.x, vB.y, hB, lB);
        Ohi[iA] = hA; Olo[iA] = lA;
        Ohi[iB] = hB; Olo[iB] = lB;
    }
}

// ===========================================================================
extern "C" void kernel_launch(void* const* d_in, const int* in_sizes, int n_in,
                              void* d_out, int out_size)
{
    const float* x      = (const float*)d_in[0];
    const float* w_qkv  = (const float*)d_in[1];
    const float* b_qkv  = (const float*)d_in[2];
    const float* w_proj = (const float*)d_in[3];
    const float* b_proj = (const float*)d_in[4];
    const float* q_a = (const float*)d_in[5];
    const float* q_b = (const float*)d_in[6];
    const float* k_a = (const float*)d_in[7];
    const float* k_b = (const float*)d_in[8];
    const float* v_a = (const float*)d_in[9];
    const float* v_b = (const float*)d_in[10];
    const float* o_a = (const float*)d_in[11];
    const float* o_b = (const float*)d_in[12];
    float* out = (float*)d_out;

    void* sym = nullptr;
    cudaGetSymbolAddress(&sym, g_scratch);
    float* base = (float*)sym;
    uint32_t* xhi = (uint32_t*)(base + F_XHI);
    uint32_t* xlo = (uint32_t*)(base + F_XLO);
    uint32_t* wqh = (uint32_t*)(base + F_WQH);
    uint32_t* wph = (uint32_t*)(base + F_WPH);
    uint32_t* Qhp = (uint32_t*)(base + F_QH);
    uint32_t* Qlp = (uint32_t*)(base + F_QL);
    uint32_t* Khp = (uint32_t*)(base + F_KH);
    uint32_t* Vhp = (uint32_t*)(base + F_VH);
    uint32_t* Ohip = (uint32_t*)(base + F_OHI);
    uint32_t* Olop = (uint32_t*)(base + F_OLO);

    cudaFuncSetAttribute(gemm_f16x2_kernel<0>, cudaFuncAttributeMaxDynamicSharedMemorySize, GEMM_SMEM);
    cudaFuncSetAttribute(gemm_f16x2_kernel<1>, cudaFuncAttributeMaxDynamicSharedMemorySize, GEMM_SMEM);
    cudaFuncSetAttribute(attn_mma_kernel, cudaFuncAttributeMaxDynamicSharedMemorySize, ATT_SMEM);

    split_kernel<<<QKV_ELEMS / 1024, 256>>>(x, xhi, xlo);
    weff_kernel<<<3 * Cdim, 128>>>(w_qkv, wqh, q_b, q_a, k_b, k_a, v_b, v_a);
    weff_kernel<<<Cdim, 128>>>(w_proj, wph, o_b, o_a, o_b, o_a, o_b, o_a);

    gemm_f16x2_kernel<0><<<dim3(18, 64), 256, GEMM_SMEM>>>(
        xhi, xlo, wqh, b_qkv, nullptr, Qhp, Qlp, Khp, Vhp);

    attn_mma_kernel<<<dim3(8, Bsz * Hh), 256, ATT_SMEM>>>(
        Qhp, Qlp, Khp, Vhp, Ohip, Olop);

    gemm_f16x2_kernel<1><<<dim3(6, 64), 256, GEMM_SMEM>>>(
        Ohip, Olop, wph, b_proj, out, nullptr, nullptr, nullptr, nullptr);
}

// round 15
// speedup vs baseline: 1.3207x; 1.1673x over previous
#include <cuda_runtime.h>
#include <cuda_fp16.h>
#include <cstdint>

#define Bsz 8
#define Nseq 1024
#define Cdim 768
#define Hh 12
#define HD 64
#define RANK 8
#define SCALE 0.125f
#define Mrows (Bsz * Nseq)          // 8192

#define QKV_ELEMS (Bsz * Hh * Nseq * HD)   // 6291456

// float-slot offsets into g_scratch
#define F_XHI  ((size_t)0)
#define F_XLO  (F_XHI + QKV_ELEMS / 2)
#define F_WQH  (F_XLO + QKV_ELEMS / 2)
#define F_WPH  (F_WQH + (size_t)(3 * Cdim * Cdim) / 2)
#define F_QH   (F_WPH + (size_t)(Cdim * Cdim) / 2)
#define F_QL   (F_QH + QKV_ELEMS / 2)
#define F_KH   (F_QL + QKV_ELEMS / 2)
#define F_VH   (F_KH + QKV_ELEMS / 2)
#define F_OHI  (F_VH + QKV_ELEMS / 2)
#define SCRATCH_FLOATS (F_OHI + QKV_ELEMS / 2)

__device__ float g_scratch[SCRATCH_FLOATS];

// ===========================================================================
// helpers
// ===========================================================================
__device__ __forceinline__ uint32_t smem_u32(const void* p) {
    uint32_t a;
    asm("{ .reg .u64 t; cvta.to.shared.u64 t, %1; cvt.u32.u64 %0, t; }" : "=r"(a) : "l"(p));
    return a;
}
__device__ __forceinline__ void cp_async16(uint32_t dst, const void* src) {
    asm volatile("cp.async.cg.shared.global [%0], [%1], 16;" :: "r"(dst), "l"(src) : "memory");
}
__device__ __forceinline__ void ldsm_x4(uint32_t* r, uint32_t addr) {
    asm volatile("ldmatrix.sync.aligned.m8n8.x4.shared.b16 {%0,%1,%2,%3}, [%4];"
        : "=r"(r[0]), "=r"(r[1]), "=r"(r[2]), "=r"(r[3]) : "r"(addr));
}
__device__ __forceinline__ void ldsm_x4_trans(uint32_t* r, uint32_t addr) {
    asm volatile("ldmatrix.sync.aligned.m8n8.x4.trans.shared.b16 {%0,%1,%2,%3}, [%4];"
        : "=r"(r[0]), "=r"(r[1]), "=r"(r[2]), "=r"(r[3]) : "r"(addr));
}
__device__ __forceinline__ void mma_f16(float* c, const uint32_t* a, const uint32_t* b) {
    asm volatile("mma.sync.aligned.m16n8k16.row.col.f32.f16.f16.f32 "
        "{%0,%1,%2,%3}, {%4,%5,%6,%7}, {%8,%9}, {%0,%1,%2,%3};"
        : "+f"(c[0]), "+f"(c[1]), "+f"(c[2]), "+f"(c[3])
        : "r"(a[0]), "r"(a[1]), "r"(a[2]), "r"(a[3]), "r"(b[0]), "r"(b[1]));
}

__device__ __forceinline__ void splitpair_h(float x, float y, uint32_t& hi, uint32_t& lo) {
    __half2 h, l;
    h.x = __float2half_rn(x);
    h.y = __float2half_rn(y);
    l.x = __float2half_rn(x - __half2float(h.x));
    l.y = __float2half_rn(y - __half2float(h.y));
    hi = *reinterpret_cast<uint32_t*>(&h);
    lo = *reinterpret_cast<uint32_t*>(&l);
}
__device__ __forceinline__ uint32_t pack2h(float x, float y) {
    __half2 h;
    h.x = __float2half_rn(x);
    h.y = __float2half_rn(y);
    return *reinterpret_cast<uint32_t*>(&h);
}

// ===========================================================================
// fp16 split (x only)
// ===========================================================================
__global__ void __launch_bounds__(256) split_kernel(
    const float* __restrict__ in, uint32_t* __restrict__ hi,
    uint32_t* __restrict__ lo)
{
    int i = blockIdx.x * 256 + threadIdx.x;
    float4 v = ((const float4*)in)[i];
    uint32_t h0, l0, h1, l1;
    splitpair_h(v.x, v.y, h0, l0);
    splitpair_h(v.z, v.w, h1, l1);
    hi[i * 2]     = h0;
    hi[i * 2 + 1] = h1;
    lo[i * 2]     = l0;
    lo[i * 2 + 1] = l1;
}

// ===========================================================================
// W_eff = W + B*A  (rank-8 update), packed to fp16 hi only.
// ===========================================================================
__global__ void __launch_bounds__(128) weff_kernel(
    const float* __restrict__ w, uint32_t* __restrict__ hi,
    const float* __restrict__ b0, const float* __restrict__ a0,
    const float* __restrict__ b1, const float* __restrict__ a1,
    const float* __restrict__ b2, const float* __restrict__ a2)
{
    int d = blockIdx.x;
    int sec = d / Cdim;
    int dd = d - sec * Cdim;
    const float* bb = (sec == 0) ? b0 : (sec == 1) ? b1 : b2;
    const float* aa = (sec == 0) ? a0 : (sec == 1) ? a1 : a2;
    float bv[8];
    #pragma unroll
    for (int r = 0; r < 8; r++) bv[r] = bb[dd * 8 + r];
    int c0 = threadIdx.x * 6;
    float v[6];
    #pragma unroll
    for (int i = 0; i < 6; i++) v[i] = w[(size_t)d * Cdim + c0 + i];
    #pragma unroll
    for (int r = 0; r < 8; r++) {
        float br = bv[r];
        const float* ar = aa + (size_t)r * Cdim + c0;
        #pragma unroll
        for (int i = 0; i < 6; i++) v[i] += br * ar[i];
    }
    #pragma unroll
    for (int p = 0; p < 3; p++)
        hi[(size_t)d * (Cdim / 2) + (c0 >> 1) + p] = pack2h(v[2 * p], v[2 * p + 1]);
}

// ===========================================================================
// fp16 NT GEMM, 128x128 tile, BK=32, 8 warps, 3-stage cp.async pipeline,
// ldmatrix frag loads, 2 CTAs/SM.
// MODE 0: A = hi+lo (2-term); qkv epilogue.
// MODE 1: A = hi only (1-term); proj epilogue.
// ===========================================================================
#define GK768_U32 384
#define SROW 20
#define STAGE_U32 (3 * 128 * SROW)          // Ahi, Alo, Bhi
#define STAGE_BYTES (STAGE_U32 * 4)         // 30720
#define NSTAGE 3
#define GEMM_SMEM (NSTAGE * STAGE_BYTES)    // 92160

template <int MODE>
__global__ void __launch_bounds__(256, 2) gemm_f16x2_kernel(
    const uint32_t* __restrict__ Ahi, const uint32_t* __restrict__ Alo,
    const uint32_t* __restrict__ Bhi,
    const float* __restrict__ bias,
    float* __restrict__ outf,
    uint32_t* __restrict__ Qho, uint32_t* __restrict__ Qlo2,
    uint32_t* __restrict__ Kho, uint32_t* __restrict__ Vho)
{
    extern __shared__ uint32_t sm[];
    uint32_t sbase = smem_u32(sm);
    int tid = threadIdx.x;
    int wid = tid >> 5, lane = tid & 31;
    int wm = wid >> 2, wn = wid & 3;
    int m0 = blockIdx.y * 128, n0 = blockIdx.x * 128;
    int g = lane >> 2, tg = lane & 3;

    float C[4][4][4];
    #pragma unroll
    for (int a = 0; a < 4; a++)
        #pragma unroll
        for (int b = 0; b < 4; b++)
            #pragma unroll
            for (int q = 0; q < 4; q++) C[a][b][q] = 0.f;

    int row_l = tid >> 2, kq_l = tid & 3;
    int row_h = (tid + 256) >> 2;

    uint32_t d0b = (row_l * SROW + kq_l * 4) * 4;
    uint32_t d1b = (row_h * SROW + kq_l * 4) * 4;
    const uint32_t* Asrc0 = Ahi + (size_t)(m0 + row_l) * GK768_U32 + kq_l * 4;
    const uint32_t* Lsrc0 = Alo + (size_t)(m0 + row_l) * GK768_U32 + kq_l * 4;
    const uint32_t* Bsrc0 = Bhi + (size_t)(n0 + row_l) * GK768_U32 + kq_l * 4;
    const uint32_t* Asrc1 = Ahi + (size_t)(m0 + row_h) * GK768_U32 + kq_l * 4;
    const uint32_t* Lsrc1 = Alo + (size_t)(m0 + row_h) * GK768_U32 + kq_l * 4;
    const uint32_t* Bsrc1 = Bhi + (size_t)(n0 + row_h) * GK768_U32 + kq_l * 4;

    uint32_t aAddr = sbase +
        (uint32_t)((wm * 64 + (lane & 7) + ((lane >> 3) & 1) * 8) * SROW * 4) +
        (uint32_t)((lane >> 4) * 16);
    uint32_t bAddr = sbase + 5120 * 4 +
        (uint32_t)((wn * 32 + (lane & 7) + ((lane & 16) >> 1)) * SROW * 4) +
        (uint32_t)(((lane >> 3) & 1) * 16);

    // prologue: chunks 0, 1
    #pragma unroll
    for (int pc = 0; pc < 2; pc++) {
        uint32_t off = pc * 16;
        uint32_t db = sbase + pc * STAGE_BYTES;
        cp_async16(db + d0b,            Asrc0 + off);
        cp_async16(db + 5120 * 4 + d0b, Bsrc0 + off);
        cp_async16(db + d1b,            Asrc1 + off);
        cp_async16(db + 5120 * 4 + d1b, Bsrc1 + off);
        if (MODE == 0) {
            cp_async16(db + 2560 * 4 + d0b, Lsrc0 + off);
            cp_async16(db + 2560 * 4 + d1b, Lsrc1 + off);
        }
        asm volatile("cp.async.commit_group;" ::: "memory");
    }

    int s = 0;
    for (int c = 0; c < 24; c++) {
        if (c < 23)
            asm volatile("cp.async.wait_group 1;" ::: "memory");
        else
            asm volatile("cp.async.wait_group 0;" ::: "memory");
        __syncthreads();

        if (c + 2 < 24) {
            uint32_t off = (c + 2) * 16;
            int sn = s + 2 - ((s + 2 >= NSTAGE) ? NSTAGE : 0);
            uint32_t db = sbase + sn * STAGE_BYTES;
            cp_async16(db + d0b,            Asrc0 + off);
            cp_async16(db + 5120 * 4 + d0b, Bsrc0 + off);
            cp_async16(db + d1b,            Asrc1 + off);
            cp_async16(db + 5120 * 4 + d1b, Bsrc1 + off);
            if (MODE == 0) {
                cp_async16(db + 2560 * 4 + d0b, Lsrc0 + off);
                cp_async16(db + 2560 * 4 + d1b, Lsrc1 + off);
            }
            asm volatile("cp.async.commit_group;" ::: "memory");
        }

        uint32_t bufo = (uint32_t)(s * STAGE_BYTES);
        #pragma unroll
        for (int ks = 0; ks < 2; ks++) {
            uint32_t ko = (uint32_t)(ks * 32);
            uint32_t ah[4][4], al[4][4], bh[4][2];
            #pragma unroll
            for (int mi = 0; mi < 4; mi++)
                ldsm_x4(ah[mi], aAddr + bufo + mi * (16 * SROW * 4) + ko);
            if (MODE == 0) {
                #pragma unroll
                for (int mi = 0; mi < 4; mi++)
                    ldsm_x4(al[mi], aAddr + bufo + 2560 * 4 + mi * (16 * SROW * 4) + ko);
            }
            #pragma unroll
            for (int p = 0; p < 2; p++) {
                uint32_t t[4];
                ldsm_x4(t, bAddr + bufo + p * (16 * SROW * 4) + ko);
                bh[2 * p][0] = t[0]; bh[2 * p][1] = t[1];
                bh[2 * p + 1][0] = t[2]; bh[2 * p + 1][1] = t[3];
            }
            #pragma unroll
            for (int mi = 0; mi < 4; mi++)
                #pragma unroll
                for (int ni = 0; ni < 4; ni++)
                    mma_f16(C[mi][ni], ah[mi], bh[ni]);
            if (MODE == 0) {
                #pragma unroll
                for (int mi = 0; mi < 4; mi++)
                    #pragma unroll
                    for (int ni = 0; ni < 4; ni++)
                        mma_f16(C[mi][ni], al[mi], bh[ni]);
            }
        }
        s = (s + 1 == NSTAGE) ? 0 : s + 1;
    }

    // ------------------------------ epilogue ------------------------------
    int sct = 0, dbase = 0;
    if (MODE == 0) {
        sct = n0 / Cdim;
        dbase = n0 - sct * Cdim;
    }
    #pragma unroll
    for (int mi = 0; mi < 4; mi++) {
        int m_a = m0 + wm * 64 + mi * 16 + g;
        int m_b = m_a + 8;
        int ba = m_a >> 10, na = m_a & 1023;
        int bb = m_b >> 10, nb = m_b & 1023;
        #pragma unroll
        for (int ni = 0; ni < 4; ni++) {
            int dloc = wn * 32 + ni * 8 + tg * 2;
            int d0 = n0 + dloc;
            float2 va, vb2;
            va.x  = C[mi][ni][0] + bias[d0];
            va.y  = C[mi][ni][1] + bias[d0 + 1];
            vb2.x = C[mi][ni][2] + bias[d0];
            vb2.y = C[mi][ni][3] + bias[d0 + 1];
            if (MODE == 0) {
                int dd0 = dbase + dloc;
                int h = dd0 >> 6, hd = dd0 & 63;
                size_t iA = (((size_t)(ba * Hh + h) * Nseq) + na) * 32 + (hd >> 1);
                size_t iB = (((size_t)(bb * Hh + h) * Nseq) + nb) * 32 + (hd >> 1);
                if (sct == 0) {
                    va.x *= SCALE; va.y *= SCALE; vb2.x *= SCALE; vb2.y *= SCALE;
                    uint32_t hA, lA, hB, lB;
                    splitpair_h(va.x, va.y, hA, lA);
                    splitpair_h(vb2.x, vb2.y, hB, lB);
                    Qho[iA] = hA; Qlo2[iA] = lA;
                    Qho[iB] = hB; Qlo2[iB] = lB;
                } else {
                    uint32_t* th = (sct == 1) ? Kho : Vho;
                    th[iA] = pack2h(va.x, va.y);
                    th[iB] = pack2h(vb2.x, vb2.y);
                }
            } else {
                *(float2*)(outf + (size_t)m_a * Cdim + d0) = va;
                *(float2*)(outf + (size_t)m_b * Cdim + d0) = vb2;
            }
        }
    }
}

// ===========================================================================
// Flash attention, fp16. S = Qhi*Kh + Qlo*Kh (2-term); PV single-term.
// K/V row-major in smem; ldmatrix + ldmatrix.trans. Output: Ohi only.
// ===========================================================================
#define KST 36
#define ATT_SMEM_U32 (2 * 128 * KST)       // 9216
#define ATT_SMEM (ATT_SMEM_U32 * 4)        // 36864

__global__ void __launch_bounds__(256) attn_mma_kernel(
    const uint32_t* __restrict__ Qh, const uint32_t* __restrict__ Ql,
    const uint32_t* __restrict__ Kh, const uint32_t* __restrict__ Vh,
    uint32_t* __restrict__ Ohi)
{
    extern __shared__ uint32_t sm[];
    uint32_t* Khs = sm;                    // 128 x 36
    uint32_t* Vhs = sm + 128 * KST;        // 128 x 36 (row-major)

    int bh = blockIdx.y, qt = blockIdx.x;
    int tid = threadIdx.x, wid = tid >> 5, lane = tid & 31;
    int g = lane >> 2, tg = lane & 3;

    uint32_t kAddr = smem_u32(Khs) +
        (uint32_t)(((lane & 7) + ((lane & 16) >> 1)) * KST * 4) +
        (uint32_t)(((lane >> 3) & 1) * 16);
    uint32_t vAddr = smem_u32(Vhs) +
        (uint32_t)((lane & 15) * KST * 4) +
        (uint32_t)((lane >> 4) * 16);

    uint32_t qh[4][4], ql[4][4];
    {
        const uint32_t* qb  = Qh + ((size_t)bh * Nseq + qt * 128 + wid * 16) * 32;
        const uint32_t* qb2 = Ql + ((size_t)bh * Nseq + qt * 128 + wid * 16) * 32;
        #pragma unroll
        for (int ks = 0; ks < 4; ks++) {
            int c0 = ks * 8 + tg;
            qh[ks][0] = qb[g * 32 + c0];        qh[ks][1] = qb[(g + 8) * 32 + c0];
            qh[ks][2] = qb[g * 32 + c0 + 4];    qh[ks][3] = qb[(g + 8) * 32 + c0 + 4];
            ql[ks][0] = qb2[g * 32 + c0];       ql[ks][1] = qb2[(g + 8) * 32 + c0];
            ql[ks][2] = qb2[g * 32 + c0 + 4];   ql[ks][3] = qb2[(g + 8) * 32 + c0 + 4];
        }
    }

    float Oa[8][4];
    #pragma unroll
    for (int i = 0; i < 8; i++)
        #pragma unroll
        for (int j = 0; j < 4; j++) Oa[i][j] = 0.f;
    float mr0 = -1e30f, mr1 = -1e30f, lr0 = 0.f, lr1 = 0.f;

    const uint32_t* kgh = Kh + (size_t)bh * Nseq * 32;
    const uint32_t* vgh = Vh + (size_t)bh * Nseq * 32;

    for (int kt = 0; kt < 8; kt++) {
        __syncthreads();
        #pragma unroll
        for (int i = 0; i < 4; i++) {
            int f = tid + i * 256;
            int key = f >> 3, c = f & 7;
            size_t gidx = ((size_t)(kt * 128 + key)) * 32 + c * 4;
            *(uint4*)(Khs + key * KST + c * 4) = *(const uint4*)(kgh + gidx);
            *(uint4*)(Vhs + key * KST + c * 4) = *(const uint4*)(vgh + gidx);
        }
        __syncthreads();

        float Sf[16][4];
        #pragma unroll
        for (int ni = 0; ni < 16; ni++)
            #pragma unroll
            for (int q = 0; q < 4; q++) Sf[ni][q] = 0.f;
        #pragma unroll
        for (int ks = 0; ks < 4; ks++) {
            uint32_t bhs[16][2];
            #pragma unroll
            for (int p = 0; p < 8; p++) {
                uint32_t t[4];
                ldsm_x4(t, kAddr + p * (16 * KST * 4) + ks * 32);
                bhs[2 * p][0] = t[0]; bhs[2 * p][1] = t[1];
                bhs[2 * p + 1][0] = t[2]; bhs[2 * p + 1][1] = t[3];
            }
            #pragma unroll
            for (int ni = 0; ni < 16; ni++)
                mma_f16(Sf[ni], qh[ks], bhs[ni]);
            #pragma unroll
            for (int ni = 0; ni < 16; ni++)
                mma_f16(Sf[ni], ql[ks], bhs[ni]);
        }

        float tm0 = -1e30f, tm1 = -1e30f;
        #pragma unroll
        for (int ni = 0; ni < 16; ni++) {
            tm0 = fmaxf(tm0, fmaxf(Sf[ni][0], Sf[ni][1]));
            tm1 = fmaxf(tm1, fmaxf(Sf[ni][2], Sf[ni][3]));
        }
        tm0 = fmaxf(tm0, __shfl_xor_sync(0xffffffffu, tm0, 1));
        tm0 = fmaxf(tm0, __shfl_xor_sync(0xffffffffu, tm0, 2));
        tm1 = fmaxf(tm1, __shfl_xor_sync(0xffffffffu, tm1, 1));
        tm1 = fmaxf(tm1, __shfl_xor_sync(0xffffffffu, tm1, 2));
        float mn0 = fmaxf(mr0, tm0), mn1 = fmaxf(mr1, tm1);
        float al0 = __expf(mr0 - mn0), al1 = __expf(mr1 - mn1);
        mr0 = mn0; mr1 = mn1;
        float s0 = 0.f, s1 = 0.f;
        #pragma unroll
        for (int ni = 0; ni < 16; ni++) {
            Sf[ni][0] = __expf(Sf[ni][0] - mn0);
            Sf[ni][1] = __expf(Sf[ni][1] - mn0);
            Sf[ni][2] = __expf(Sf[ni][2] - mn1);
            Sf[ni][3] = __expf(Sf[ni][3] - mn1);
            s0 += Sf[ni][0] + Sf[ni][1];
            s1 += Sf[ni][2] + Sf[ni][3];
        }
        s0 += __shfl_xor_sync(0xffffffffu, s0, 1);
        s0 += __shfl_xor_sync(0xffffffffu, s0, 2);
        s1 += __shfl_xor_sync(0xffffffffu, s1, 1);
        s1 += __shfl_xor_sync(0xffffffffu, s1, 2);
        lr0 = lr0 * al0 + s0;
        lr1 = lr1 * al1 + s1;
        #pragma unroll
        for (int ni = 0; ni < 8; ni++) {
            Oa[ni][0] *= al0; Oa[ni][1] *= al0;
            Oa[ni][2] *= al1; Oa[ni][3] *= al1;
        }

        // O += P V, single-term P (fp16), ldmatrix.trans V frags
        #pragma unroll
        for (int j = 0; j < 8; j++) {
            uint32_t ph[4];
            ph[0] = pack2h(Sf[2*j][0],   Sf[2*j][1]);
            ph[1] = pack2h(Sf[2*j][2],   Sf[2*j][3]);
            ph[2] = pack2h(Sf[2*j+1][0], Sf[2*j+1][1]);
            ph[3] = pack2h(Sf[2*j+1][2], Sf[2*j+1][3]);
            uint32_t vf[8][2];
            #pragma unroll
            for (int p = 0; p < 4; p++) {
                uint32_t t[4];
                ldsm_x4_trans(t, vAddr + j * (16 * KST * 4) + p * 32);
                vf[2 * p][0] = t[0]; vf[2 * p][1] = t[1];
                vf[2 * p + 1][0] = t[2]; vf[2 * p + 1][1] = t[3];
            }
            #pragma unroll
            for (int ni = 0; ni < 8; ni++)
                mma_f16(Oa[ni], ph, vf[ni]);
        }
    }

    // epilogue: Ohi fp16 only, [m][C] packed u32
    float inv0 = 1.f / lr0, inv1 = 1.f / lr1;
    int b = bh / Hh, h = bh % Hh;
    int nA = qt * 128 + wid * 16 + g;
    int nB = nA + 8;
    #pragma unroll
    for (int ni = 0; ni < 8; ni++) {
        int hd = ni * 8 + tg * 2;
        size_t iA = (((size_t)b * Nseq + nA) * Cdim + h * HD + hd) >> 1;
        size_t iB = (((size_t)b * Nseq + nB) * Cdim + h * HD + hd) >> 1;
        Ohi[iA] = pack2h(Oa[ni][0] * inv0, Oa[ni][1] * inv0);
        Ohi[iB] = pack2h(Oa[ni][2] * inv1, Oa[ni][3] * inv1);
    }
}

// ===========================================================================
extern "C" void kernel_launch(void* const* d_in, const int* in_sizes, int n_in,
                              void* d_out, int out_size)
{
    const float* x      = (const float*)d_in[0];
    const float* w_qkv  = (const float*)d_in[1];
    const float* b_qkv  = (const float*)d_in[2];
    const float* w_proj = (const float*)d_in[3];
    const float* b_proj = (const float*)d_in[4];
    const float* q_a = (const float*)d_in[5];
    const float* q_b = (const float*)d_in[6];
    const float* k_a = (const float*)d_in[7];
    const float* k_b = (const float*)d_in[8];
    const float* v_a = (const float*)d_in[9];
    const float* v_b = (const float*)d_in[10];
    const float* o_a = (const float*)d_in[11];
    const float* o_b = (const float*)d_in[12];
    float* out = (float*)d_out;

    void* sym = nullptr;
    cudaGetSymbolAddress(&sym, g_scratch);
    float* base = (float*)sym;
    uint32_t* xhi = (uint32_t*)(base + F_XHI);
    uint32_t* xlo = (uint32_t*)(base + F_XLO);
    uint32_t* wqh = (uint32_t*)(base + F_WQH);
    uint32_t* wph = (uint32_t*)(base + F_WPH);
    uint32_t* Qhp = (uint32_t*)(base + F_QH);
    uint32_t* Qlp = (uint32_t*)(base + F_QL);
    uint32_t* Khp = (uint32_t*)(base + F_KH);
    uint32_t* Vhp = (uint32_t*)(base + F_VH);
    uint32_t* Ohip = (uint32_t*)(base + F_OHI);

    cudaFuncSetAttribute(gemm_f16x2_kernel<0>, cudaFuncAttributeMaxDynamicSharedMemorySize, GEMM_SMEM);
    cudaFuncSetAttribute(gemm_f16x2_kernel<1>, cudaFuncAttributeMaxDynamicSharedMemorySize, GEMM_SMEM);
    cudaFuncSetAttribute(attn_mma_kernel, cudaFuncAttributeMaxDynamicSharedMemorySize, ATT_SMEM);

    split_kernel<<<QKV_ELEMS / 1024, 256>>>(x, xhi, xlo);
    weff_kernel<<<3 * Cdim, 128>>>(w_qkv, wqh, q_b, q_a, k_b, k_a, v_b, v_a);
    weff_kernel<<<Cdim, 128>>>(w_proj, wph, o_b, o_a, o_b, o_a, o_b, o_a);

    gemm_f16x2_kernel<0><<<dim3(18, 64), 256, GEMM_SMEM>>>(
        xhi, xlo, wqh, b_qkv, nullptr, Qhp, Qlp, Khp, Vhp);

    attn_mma_kernel<<<dim3(8, Bsz * Hh), 256, ATT_SMEM>>>(
        Qhp, Qlp, Khp, Vhp, Ohip);

    gemm_f16x2_kernel<1><<<dim3(6, 64), 256, GEMM_SMEM>>>(
        Ohip, Ohip, wph, b_proj, out, nullptr, nullptr, nullptr, nullptr);
}

// round 17
// speedup vs baseline: 1.4109x; 1.0684x over previous
#include <cuda_runtime.h>
#include <cuda_fp16.h>
#include <cstdint>

#define Bsz 8
#define Nseq 1024
#define Cdim 768
#define Hh 12
#define HD 64
#define RANK 8
#define SCALE 0.125f
#define Mrows (Bsz * Nseq)          // 8192

#define QKV_ELEMS (Bsz * Hh * Nseq * HD)   // 6291456

// float-slot offsets into g_scratch
#define F_XHI  ((size_t)0)
#define F_XLO  (F_XHI + QKV_ELEMS / 2)
#define F_WQH  (F_XLO + QKV_ELEMS / 2)
#define F_WPH  (F_WQH + (size_t)(3 * Cdim * Cdim) / 2)
#define F_QH   (F_WPH + (size_t)(Cdim * Cdim) / 2)
#define F_QL   (F_QH + QKV_ELEMS / 2)
#define F_KH   (F_QL + QKV_ELEMS / 2)
#define F_VH   (F_KH + QKV_ELEMS / 2)
#define F_OHI  (F_VH + QKV_ELEMS / 2)
#define SCRATCH_FLOATS (F_OHI + QKV_ELEMS / 2)

__device__ float g_scratch[SCRATCH_FLOATS];

// ===========================================================================
// helpers
// ===========================================================================
__device__ __forceinline__ uint32_t smem_u32(const void* p) {
    uint32_t a;
    asm("{ .reg .u64 t; cvta.to.shared.u64 t, %1; cvt.u32.u64 %0, t; }" : "=r"(a) : "l"(p));
    return a;
}
__device__ __forceinline__ void cp_async16(uint32_t dst, const void* src) {
    asm volatile("cp.async.cg.shared.global [%0], [%1], 16;" :: "r"(dst), "l"(src) : "memory");
}
__device__ __forceinline__ void ldsm_x4(uint32_t* r, uint32_t addr) {
    asm volatile("ldmatrix.sync.aligned.m8n8.x4.shared.b16 {%0,%1,%2,%3}, [%4];"
        : "=r"(r[0]), "=r"(r[1]), "=r"(r[2]), "=r"(r[3]) : "r"(addr));
}
__device__ __forceinline__ void ldsm_x4_trans(uint32_t* r, uint32_t addr) {
    asm volatile("ldmatrix.sync.aligned.m8n8.x4.trans.shared.b16 {%0,%1,%2,%3}, [%4];"
        : "=r"(r[0]), "=r"(r[1]), "=r"(r[2]), "=r"(r[3]) : "r"(addr));
}
__device__ __forceinline__ void mma_f16(float* c, const uint32_t* a, const uint32_t* b) {
    asm volatile("mma.sync.aligned.m16n8k16.row.col.f32.f16.f16.f32 "
        "{%0,%1,%2,%3}, {%4,%5,%6,%7}, {%8,%9}, {%0,%1,%2,%3};"
        : "+f"(c[0]), "+f"(c[1]), "+f"(c[2]), "+f"(c[3])
        : "r"(a[0]), "r"(a[1]), "r"(a[2]), "r"(a[3]), "r"(b[0]), "r"(b[1]));
}

__device__ __forceinline__ void splitpair_h(float x, float y, uint32_t& hi, uint32_t& lo) {
    __half2 h, l;
    h.x = __float2half_rn(x);
    h.y = __float2half_rn(y);
    l.x = __float2half_rn(x - __half2float(h.x));
    l.y = __float2half_rn(y - __half2float(h.y));
    hi = *reinterpret_cast<uint32_t*>(&h);
    lo = *reinterpret_cast<uint32_t*>(&l);
}
__device__ __forceinline__ uint32_t pack2h(float x, float y) {
    __half2 h;
    h.x = __float2half_rn(x);
    h.y = __float2half_rn(y);
    return *reinterpret_cast<uint32_t*>(&h);
}

// ===========================================================================
// fp16 split (x only)
// ===========================================================================
__global__ void __launch_bounds__(256) split_kernel(
    const float* __restrict__ in, uint32_t* __restrict__ hi,
    uint32_t* __restrict__ lo)
{
    int i = blockIdx.x * 256 + threadIdx.x;
    float4 v = ((const float4*)in)[i];
    uint32_t h0, l0, h1, l1;
    splitpair_h(v.x, v.y, h0, l0);
    splitpair_h(v.z, v.w, h1, l1);
    hi[i * 2]     = h0;
    hi[i * 2 + 1] = h1;
    lo[i * 2]     = l0;
    lo[i * 2 + 1] = l1;
}

// ===========================================================================
// W_eff = W + B*A  (rank-8 update), packed to fp16 hi only.
// ===========================================================================
__global__ void __launch_bounds__(128) weff_kernel(
    const float* __restrict__ w, uint32_t* __restrict__ hi,
    const float* __restrict__ b0, const float* __restrict__ a0,
    const float* __restrict__ b1, const float* __restrict__ a1,
    const float* __restrict__ b2, const float* __restrict__ a2)
{
    int d = blockIdx.x;
    int sec = d / Cdim;
    int dd = d - sec * Cdim;
    const float* bb = (sec == 0) ? b0 : (sec == 1) ? b1 : b2;
    const float* aa = (sec == 0) ? a0 : (sec == 1) ? a1 : a2;
    float bv[8];
    #pragma unroll
    for (int r = 0; r < 8; r++) bv[r] = bb[dd * 8 + r];
    int c0 = threadIdx.x * 6;
    float v[6];
    #pragma unroll
    for (int i = 0; i < 6; i++) v[i] = w[(size_t)d * Cdim + c0 + i];
    #pragma unroll
    for (int r = 0; r < 8; r++) {
        float br = bv[r];
        const float* ar = aa + (size_t)r * Cdim + c0;
        #pragma unroll
        for (int i = 0; i < 6; i++) v[i] += br * ar[i];
    }
    #pragma unroll
    for (int p = 0; p < 3; p++)
        hi[(size_t)d * (Cdim / 2) + (c0 >> 1) + p] = pack2h(v[2 * p], v[2 * p + 1]);
}

// ===========================================================================
// fp16 NT GEMM, 128x128 tile, BK=32, 8 warps, 3-stage cp.async pipeline,
// ldmatrix frag loads, 2 CTAs/SM.
// MODE 0: qkv epilogue (sector = (NCOL0+n0)/Cdim); NTERM = 2 (Q) or 1 (K/V)
// MODE 1: proj epilogue, NTERM 1.
// B/bias pointers are passed pre-offset by NCOL0 rows/elements.
// ===========================================================================
#define GK768_U32 384
#define SROW 20
#define STAGE_U32 (3 * 128 * SROW)          // Ahi, Alo, Bhi
#define STAGE_BYTES (STAGE_U32 * 4)         // 30720
#define NSTAGE 3
#define GEMM_SMEM (NSTAGE * STAGE_BYTES)    // 92160

template <int MODE, int NTERM, int NCOL0>
__global__ void __launch_bounds__(256, 2) gemm_f16_kernel(
    const uint32_t* __restrict__ Ahi, const uint32_t* __restrict__ Alo,
    const uint32_t* __restrict__ Bhi,
    const float* __restrict__ bias,
    float* __restrict__ outf,
    uint32_t* __restrict__ Qho, uint32_t* __restrict__ Qlo2,
    uint32_t* __restrict__ Kho, uint32_t* __restrict__ Vho)
{
    extern __shared__ uint32_t sm[];
    uint32_t sbase = smem_u32(sm);
    int tid = threadIdx.x;
    int wid = tid >> 5, lane = tid & 31;
    int wm = wid >> 2, wn = wid & 3;
    int m0 = blockIdx.y * 128, n0 = blockIdx.x * 128;
    int g = lane >> 2, tg = lane & 3;

    float C[4][4][4];
    #pragma unroll
    for (int a = 0; a < 4; a++)
        #pragma unroll
        for (int b = 0; b < 4; b++)
            #pragma unroll
            for (int q = 0; q < 4; q++) C[a][b][q] = 0.f;

    int row_l = tid >> 2, kq_l = tid & 3;
    int row_h = (tid + 256) >> 2;

    uint32_t d0b = (row_l * SROW + kq_l * 4) * 4;
    uint32_t d1b = (row_h * SROW + kq_l * 4) * 4;
    const uint32_t* Asrc0 = Ahi + (size_t)(m0 + row_l) * GK768_U32 + kq_l * 4;
    const uint32_t* Lsrc0 = Alo + (size_t)(m0 + row_l) * GK768_U32 + kq_l * 4;
    const uint32_t* Bsrc0 = Bhi + (size_t)(n0 + row_l) * GK768_U32 + kq_l * 4;
    const uint32_t* Asrc1 = Ahi + (size_t)(m0 + row_h) * GK768_U32 + kq_l * 4;
    const uint32_t* Lsrc1 = Alo + (size_t)(m0 + row_h) * GK768_U32 + kq_l * 4;
    const uint32_t* Bsrc1 = Bhi + (size_t)(n0 + row_h) * GK768_U32 + kq_l * 4;

    uint32_t aAddr = sbase +
        (uint32_t)((wm * 64 + (lane & 7) + ((lane >> 3) & 1) * 8) * SROW * 4) +
        (uint32_t)((lane >> 4) * 16);
    uint32_t bAddr = sbase + 5120 * 4 +
        (uint32_t)((wn * 32 + (lane & 7) + ((lane & 16) >> 1)) * SROW * 4) +
        (uint32_t)(((lane >> 3) & 1) * 16);

    // prologue: chunks 0, 1
    #pragma unroll
    for (int pc = 0; pc < 2; pc++) {
        uint32_t off = pc * 16;
        uint32_t db = sbase + pc * STAGE_BYTES;
        cp_async16(db + d0b,            Asrc0 + off);
        cp_async16(db + 5120 * 4 + d0b, Bsrc0 + off);
        cp_async16(db + d1b,            Asrc1 + off);
        cp_async16(db + 5120 * 4 + d1b, Bsrc1 + off);
        if (NTERM == 2) {
            cp_async16(db + 2560 * 4 + d0b, Lsrc0 + off);
            cp_async16(db + 2560 * 4 + d1b, Lsrc1 + off);
        }
        asm volatile("cp.async.commit_group;" ::: "memory");
    }

    int s = 0;
    for (int c = 0; c < 24; c++) {
        if (c < 23)
            asm volatile("cp.async.wait_group 1;" ::: "memory");
        else
            asm volatile("cp.async.wait_group 0;" ::: "memory");
        __syncthreads();

        if (c + 2 < 24) {
            uint32_t off = (c + 2) * 16;
            int sn = s + 2 - ((s + 2 >= NSTAGE) ? NSTAGE : 0);
            uint32_t db = sbase + sn * STAGE_BYTES;
            cp_async16(db + d0b,            Asrc0 + off);
            cp_async16(db + 5120 * 4 + d0b, Bsrc0 + off);
            cp_async16(db + d1b,            Asrc1 + off);
            cp_async16(db + 5120 * 4 + d1b, Bsrc1 + off);
            if (NTERM == 2) {
                cp_async16(db + 2560 * 4 + d0b, Lsrc0 + off);
                cp_async16(db + 2560 * 4 + d1b, Lsrc1 + off);
            }
            asm volatile("cp.async.commit_group;" ::: "memory");
        }

        uint32_t bufo = (uint32_t)(s * STAGE_BYTES);
        #pragma unroll
        for (int ks = 0; ks < 2; ks++) {
            uint32_t ko = (uint32_t)(ks * 32);
            uint32_t ah[4][4], al[4][4], bh[4][2];
            #pragma unroll
            for (int mi = 0; mi < 4; mi++)
                ldsm_x4(ah[mi], aAddr + bufo + mi * (16 * SROW * 4) + ko);
            if (NTERM == 2) {
                #pragma unroll
                for (int mi = 0; mi < 4; mi++)
                    ldsm_x4(al[mi], aAddr + bufo + 2560 * 4 + mi * (16 * SROW * 4) + ko);
            }
            #pragma unroll
            for (int p = 0; p < 2; p++) {
                uint32_t t[4];
                ldsm_x4(t, bAddr + bufo + p * (16 * SROW * 4) + ko);
                bh[2 * p][0] = t[0]; bh[2 * p][1] = t[1];
                bh[2 * p + 1][0] = t[2]; bh[2 * p + 1][1] = t[3];
            }
            #pragma unroll
            for (int mi = 0; mi < 4; mi++)
                #pragma unroll
                for (int ni = 0; ni < 4; ni++)
                    mma_f16(C[mi][ni], ah[mi], bh[ni]);
            if (NTERM == 2) {
                #pragma unroll
                for (int mi = 0; mi < 4; mi++)
                    #pragma unroll
                    for (int ni = 0; ni < 4; ni++)
                        mma_f16(C[mi][ni], al[mi], bh[ni]);
            }
        }
        s = (s + 1 == NSTAGE) ? 0 : s + 1;
    }

    // ------------------------------ epilogue ------------------------------
    int sct = 0, dbase = 0;
    if (MODE == 0) {
        sct = (NCOL0 + n0) / Cdim;
        dbase = NCOL0 + n0 - sct * Cdim;
    }
    #pragma unroll
    for (int mi = 0; mi < 4; mi++) {
        int m_a = m0 + wm * 64 + mi * 16 + g;
        int m_b = m_a + 8;
        int ba = m_a >> 10, na = m_a & 1023;
        int bb = m_b >> 10, nb = m_b & 1023;
        #pragma unroll
        for (int ni = 0; ni < 4; ni++) {
            int dloc = wn * 32 + ni * 8 + tg * 2;
            int d0 = n0 + dloc;
            float2 va, vb2;
            va.x  = C[mi][ni][0] + bias[d0];
            va.y  = C[mi][ni][1] + bias[d0 + 1];
            vb2.x = C[mi][ni][2] + bias[d0];
            vb2.y = C[mi][ni][3] + bias[d0 + 1];
            if (MODE == 0) {
                int dd0 = dbase + dloc;
                int h = dd0 >> 6, hd = dd0 & 63;
                size_t iA = (((size_t)(ba * Hh + h) * Nseq) + na) * 32 + (hd >> 1);
                size_t iB = (((size_t)(bb * Hh + h) * Nseq) + nb) * 32 + (hd >> 1);
                if (sct == 0) {
                    va.x *= SCALE; va.y *= SCALE; vb2.x *= SCALE; vb2.y *= SCALE;
                    uint32_t hA, lA, hB, lB;
                    splitpair_h(va.x, va.y, hA, lA);
                    splitpair_h(vb2.x, vb2.y, hB, lB);
                    Qho[iA] = hA; Qlo2[iA] = lA;
                    Qho[iB] = hB; Qlo2[iB] = lB;
                } else {
                    uint32_t* th = (sct == 1) ? Kho : Vho;
                    th[iA] = pack2h(va.x, va.y);
                    th[iB] = pack2h(vb2.x, vb2.y);
                }
            } else {
                *(float2*)(outf + (size_t)m_a * Cdim + d0) = va;
                *(float2*)(outf + (size_t)m_b * Cdim + d0) = vb2;
            }
        }
    }
}

// ===========================================================================
// Flash attention (R15 version): S 2-term, PV single-term, Ohi output.
// ===========================================================================
#define KST 36
#define ATT_SMEM_U32 (2 * 128 * KST)       // 9216
#define ATT_SMEM (ATT_SMEM_U32 * 4)        // 36864

__global__ void __launch_bounds__(256) attn_mma_kernel(
    const uint32_t* __restrict__ Qh, const uint32_t* __restrict__ Ql,
    const uint32_t* __restrict__ Kh, const uint32_t* __restrict__ Vh,
    uint32_t* __restrict__ Ohi)
{
    extern __shared__ uint32_t sm[];
    uint32_t* Khs = sm;
    uint32_t* Vhs = sm + 128 * KST;

    int bh = blockIdx.y, qt = blockIdx.x;
    int tid = threadIdx.x, wid = tid >> 5, lane = tid & 31;
    int g = lane >> 2, tg = lane & 3;

    uint32_t kAddr = smem_u32(Khs) +
        (uint32_t)(((lane & 7) + ((lane & 16) >> 1)) * KST * 4) +
        (uint32_t)(((lane >> 3) & 1) * 16);
    uint32_t vAddr = smem_u32(Vhs) +
        (uint32_t)((lane & 15) * KST * 4) +
        (uint32_t)((lane >> 4) * 16);

    uint32_t qh[4][4], ql[4][4];
    {
        const uint32_t* qb  = Qh + ((size_t)bh * Nseq + qt * 128 + wid * 16) * 32;
        const uint32_t* qb2 = Ql + ((size_t)bh * Nseq + qt * 128 + wid * 16) * 32;
        #pragma unroll
        for (int ks = 0; ks < 4; ks++) {
            int c0 = ks * 8 + tg;
            qh[ks][0] = qb[g * 32 + c0];        qh[ks][1] = qb[(g + 8) * 32 + c0];
            qh[ks][2] = qb[g * 32 + c0 + 4];    qh[ks][3] = qb[(g + 8) * 32 + c0 + 4];
            ql[ks][0] = qb2[g * 32 + c0];       ql[ks][1] = qb2[(g + 8) * 32 + c0];
            ql[ks][2] = qb2[g * 32 + c0 + 4];   ql[ks][3] = qb2[(g + 8) * 32 + c0 + 4];
        }
    }

    float Oa[8][4];
    #pragma unroll
    for (int i = 0; i < 8; i++)
        #pragma unroll
        for (int j = 0; j < 4; j++) Oa[i][j] = 0.f;
    float mr0 = -1e30f, mr1 = -1e30f, lr0 = 0.f, lr1 = 0.f;

    const uint32_t* kgh = Kh + (size_t)bh * Nseq * 32;
    const uint32_t* vgh = Vh + (size_t)bh * Nseq * 32;

    for (int kt = 0; kt < 8; kt++) {
        __syncthreads();
        #pragma unroll
        for (int i = 0; i < 4; i++) {
            int f = tid + i * 256;
            int key = f >> 3, c = f & 7;
            size_t gidx = ((size_t)(kt * 128 + key)) * 32 + c * 4;
            *(uint4*)(Khs + key * KST + c * 4) = *(const uint4*)(kgh + gidx);
            *(uint4*)(Vhs + key * KST + c * 4) = *(const uint4*)(vgh + gidx);
        }
        __syncthreads();

        float Sf[16][4];
        #pragma unroll
        for (int ni = 0; ni < 16; ni++)
            #pragma unroll
            for (int q = 0; q < 4; q++) Sf[ni][q] = 0.f;
        #pragma unroll
        for (int ks = 0; ks < 4; ks++) {
            uint32_t bhs[16][2];
            #pragma unroll
            for (int p = 0; p < 8; p++) {
                uint32_t t[4];
                ldsm_x4(t, kAddr + p * (16 * KST * 4) + ks * 32);
                bhs[2 * p][0] = t[0]; bhs[2 * p][1] = t[1];
                bhs[2 * p + 1][0] = t[2]; bhs[2 * p + 1][1] = t[3];
            }
            #pragma unroll
            for (int ni = 0; ni < 16; ni++)
                mma_f16(Sf[ni], qh[ks], bhs[ni]);
            #pragma unroll
            for (int ni = 0; ni < 16; ni++)
                mma_f16(Sf[ni], ql[ks], bhs[ni]);
        }

        float tm0 = -1e30f, tm1 = -1e30f;
        #pragma unroll
        for (int ni = 0; ni < 16; ni++) {
            tm0 = fmaxf(tm0, fmaxf(Sf[ni][0], Sf[ni][1]));
            tm1 = fmaxf(tm1, fmaxf(Sf[ni][2], Sf[ni][3]));
        }
        tm0 = fmaxf(tm0, __shfl_xor_sync(0xffffffffu, tm0, 1));
        tm0 = fmaxf(tm0, __shfl_xor_sync(0xffffffffu, tm0, 2));
        tm1 = fmaxf(tm1, __shfl_xor_sync(0xffffffffu, tm1, 1));
        tm1 = fmaxf(tm1, __shfl_xor_sync(0xffffffffu, tm1, 2));
        float mn0 = fmaxf(mr0, tm0), mn1 = fmaxf(mr1, tm1);
        float al0 = __expf(mr0 - mn0), al1 = __expf(mr1 - mn1);
        mr0 = mn0; mr1 = mn1;
        float s0 = 0.f, s1 = 0.f;
        #pragma unroll
        for (int ni = 0; ni < 16; ni++) {
            Sf[ni][0] = __expf(Sf[ni][0] - mn0);
            Sf[ni][1] = __expf(Sf[ni][1] - mn0);
            Sf[ni][2] = __expf(Sf[ni][2] - mn1);
            Sf[ni][3] = __expf(Sf[ni][3] - mn1);
            s0 += Sf[ni][0] + Sf[ni][1];
            s1 += Sf[ni][2] + Sf[ni][3];
        }
        s0 += __shfl_xor_sync(0xffffffffu, s0, 1);
        s0 += __shfl_xor_sync(0xffffffffu, s0, 2);
        s1 += __shfl_xor_sync(0xffffffffu, s1, 1);
        s1 += __shfl_xor_sync(0xffffffffu, s1, 2);
        lr0 = lr0 * al0 + s0;
        lr1 = lr1 * al1 + s1;
        #pragma unroll
        for (int ni = 0; ni < 8; ni++) {
            Oa[ni][0] *= al0; Oa[ni][1] *= al0;
            Oa[ni][2] *= al1; Oa[ni][3] *= al1;
        }

        #pragma unroll
        for (int j = 0; j < 8; j++) {
            uint32_t ph[4];
            ph[0] = pack2h(Sf[2*j][0],   Sf[2*j][1]);
            ph[1] = pack2h(Sf[2*j][2],   Sf[2*j][3]);
            ph[2] = pack2h(Sf[2*j+1][0], Sf[2*j+1][1]);
            ph[3] = pack2h(Sf[2*j+1][2], Sf[2*j+1][3]);
            uint32_t vf[8][2];
            #pragma unroll
            for (int p = 0; p < 4; p++) {
                uint32_t t[4];
                ldsm_x4_trans(t, vAddr + j * (16 * KST * 4) + p * 32);
                vf[2 * p][0] = t[0]; vf[2 * p][1] = t[1];
                vf[2 * p + 1][0] = t[2]; vf[2 * p + 1][1] = t[3];
            }
            #pragma unroll
            for (int ni = 0; ni < 8; ni++)
                mma_f16(Oa[ni], ph, vf[ni]);
        }
    }

    float inv0 = 1.f / lr0, inv1 = 1.f / lr1;
    int b = bh / Hh, h = bh % Hh;
    int nA = qt * 128 + wid * 16 + g;
    int nB = nA + 8;
    #pragma unroll
    for (int ni = 0; ni < 8; ni++) {
        int hd = ni * 8 + tg * 2;
        size_t iA = (((size_t)b * Nseq + nA) * Cdim + h * HD + hd) >> 1;
        size_t iB = (((size_t)b * Nseq + nB) * Cdim + h * HD + hd) >> 1;
        Ohi[iA] = pack2h(Oa[ni][0] * inv0, Oa[ni][1] * inv0);
        Ohi[iB] = pack2h(Oa[ni][2] * inv1, Oa[ni][3] * inv1);
    }
}

// ===========================================================================
extern "C" void kernel_launch(void* const* d_in, const int* in_sizes, int n_in,
                              void* d_out, int out_size)
{
    const float* x      = (const float*)d_in[0];
    const float* w_qkv  = (const float*)d_in[1];
    const float* b_qkv  = (const float*)d_in[2];
    const float* w_proj = (const float*)d_in[3];
    const float* b_proj = (const float*)d_in[4];
    const float* q_a = (const float*)d_in[5];
    const float* q_b = (const float*)d_in[6];
    const float* k_a = (const float*)d_in[7];
    const float* k_b = (const float*)d_in[8];
    const float* v_a = (const float*)d_in[9];
    const float* v_b = (const float*)d_in[10];
    const float* o_a = (const float*)d_in[11];
    const float* o_b = (const float*)d_in[12];
    float* out = (float*)d_out;

    void* sym = nullptr;
    cudaGetSymbolAddress(&sym, g_scratch);
    float* base = (float*)sym;
    uint32_t* xhi = (uint32_t*)(base + F_XHI);
    uint32_t* xlo = (uint32_t*)(base + F_XLO);
    uint32_t* wqh = (uint32_t*)(base + F_WQH);
    uint32_t* wph = (uint32_t*)(base + F_WPH);
    uint32_t* Qhp = (uint32_t*)(base + F_QH);
    uint32_t* Qlp = (uint32_t*)(base + F_QL);
    uint32_t* Khp = (uint32_t*)(base + F_KH);
    uint32_t* Vhp = (uint32_t*)(base + F_VH);
    uint32_t* Ohip = (uint32_t*)(base + F_OHI);

    cudaFuncSetAttribute((const void*)gemm_f16_kernel<0, 2, 0>,
        cudaFuncAttributeMaxDynamicSharedMemorySize, GEMM_SMEM);
    cudaFuncSetAttribute((const void*)gemm_f16_kernel<0, 1, Cdim>,
        cudaFuncAttributeMaxDynamicSharedMemorySize, GEMM_SMEM);
    cudaFuncSetAttribute((const void*)gemm_f16_kernel<1, 1, 0>,
        cudaFuncAttributeMaxDynamicSharedMemorySize, GEMM_SMEM);
    cudaFuncSetAttribute(attn_mma_kernel, cudaFuncAttributeMaxDynamicSharedMemorySize, ATT_SMEM);

    split_kernel<<<QKV_ELEMS / 1024, 256>>>(x, xhi, xlo);
    weff_kernel<<<3 * Cdim, 128>>>(w_qkv, wqh, q_b, q_a, k_b, k_a, v_b, v_a);
    weff_kernel<<<Cdim, 128>>>(w_proj, wph, o_b, o_a, o_b, o_a, o_b, o_a);

    // Q sector: 2-term A (precision feeds the exp-amplified S path)
    gemm_f16_kernel<0, 2, 0><<<dim3(6, 64), 256, GEMM_SMEM>>>(
        xhi, xlo, wqh, b_qkv, nullptr, Qhp, Qlp, Khp, Vhp);

    // K/V sectors: 1-term A (output is stored hi-only anyway)
    gemm_f16_kernel<0, 1, Cdim><<<dim3(12, 64), 256, GEMM_SMEM>>>(
        xhi, xlo, wqh + (size_t)Cdim * GK768_U32, b_qkv + Cdim,
        nullptr, Qhp, Qlp, Khp, Vhp);

    attn_mma_kernel<<<dim3(8, Bsz * Hh), 256, ATT_SMEM>>>(
        Qhp, Qlp, Khp, Vhp, Ohip);

    gemm_f16_kernel<1, 1, 0><<<dim3(6, 64), 256, GEMM_SMEM>>>(
        Ohip, Ohip, wph, b_proj, out, nullptr, nullptr, nullptr, nullptr);
}